// round 6
// baseline (speedup 1.0000x reference)
#include <cuda_runtime.h>
#include <cuda_bf16.h>

// ---------------- problem constants ----------------
#define NN 20000
#define EE 320000
// L1: 768->1536, L2: 1536->768, L3: 768->384, L4: 384->256, L5: 256->5

// ---------------- scratch (device globals; 245.8MB total) ----------------
__device__ float g_P[(size_t)NN * 768];    // pre-aggregation linear output (chunked)
__device__ float g_A[(size_t)NN * 1536];   // activation ping (h1 / h3)
__device__ float g_B[(size_t)NN * 768];    // activation pong (h2)
__device__ float g_dinv[NN];
__device__ int   g_deg[NN];
__device__ int   g_rowptr[NN + 1];
__device__ int   g_cursor[NN];
__device__ int   g_csrc[EE];

// ---------------- CSR build ----------------
__global__ void k_zero_int() {
    int i = blockIdx.x * blockDim.x + threadIdx.x;
    if (i < NN) { g_deg[i] = 0; g_cursor[i] = 0; }
}

// NOTE: edge_index is int32 on device (JAX downcasts int64 without x64 mode).
__global__ void k_count(const int* __restrict__ ei) {
    int e = blockIdx.x * blockDim.x + threadIdx.x;
    if (e < EE) atomicAdd(&g_deg[ei[EE + e]], 1);
}

// single block, 1024 threads: exclusive scan of degrees + dinv
__global__ void k_scan() {
    __shared__ int sh[1024];
    int tid = threadIdx.x;
    int lo = tid * 20;
    int hi = lo + 20; if (hi > NN) hi = NN; if (lo > NN) lo = NN;
    int s = 0;
    for (int i = lo; i < hi; i++) s += g_deg[i];
    sh[tid] = s;
    __syncthreads();
    for (int off = 1; off < 1024; off <<= 1) {
        int v = (tid >= off) ? sh[tid - off] : 0;
        __syncthreads();
        sh[tid] += v;
        __syncthreads();
    }
    int run = (tid > 0) ? sh[tid - 1] : 0;
    for (int i = lo; i < hi; i++) {
        g_rowptr[i] = run;
        int d = g_deg[i];
        run += d;
        g_dinv[i] = 1.0f / fmaxf((float)d, 1.0f);
    }
    if (tid == 0) g_rowptr[NN] = EE;
}

__global__ void k_fill(const int* __restrict__ ei) {
    int e = blockIdx.x * blockDim.x + threadIdx.x;
    if (e < EE) {
        int dst = ei[EE + e];
        int pos = atomicAdd(&g_cursor[dst], 1);
        g_csrc[g_rowptr[dst] + pos] = ei[e];
    }
}

// sort each node's src list (insertion sort; avg degree 16) -> deterministic sums
__global__ void k_sort() {
    int n = blockIdx.x * blockDim.x + threadIdx.x;
    if (n >= NN) return;
    int b = g_rowptr[n], t = g_rowptr[n + 1];
    for (int i = b + 1; i < t; i++) {
        int v = g_csrc[i];
        int j = i - 1;
        while (j >= b && g_csrc[j] > v) { g_csrc[j + 1] = g_csrc[j]; j--; }
        g_csrc[j + 1] = v;
    }
}

// ---------------- GEMM: C[:, ccol0:+Nc] = A[M,K] @ B (+bias), no relu ----------------
// INS: 0=g_A, 1=g_B, 2=external.  OUTS: 0=g_P, 1=g_A, 2=g_B, 3=external.
template <int INS, int OUTS>
__global__ void __launch_bounds__(256)
k_gemm(const float* extA, float* extC,
       const float* __restrict__ Bw, const float* __restrict__ bias,
       int M, int K, int Nc, int ldb, int ldc, int ccol0) {
    const float* A;
    if constexpr (INS == 0)      A = g_A;
    else if constexpr (INS == 1) A = g_B;
    else                         A = extA;
    float* C;
    if constexpr (OUTS == 0)      C = g_P;
    else if constexpr (OUTS == 1) C = g_A;
    else if constexpr (OUTS == 2) C = g_B;
    else                          C = extC;

    __shared__ float As[16][64];
    __shared__ float Bs[16][65];

    int tid = threadIdx.x;
    int tx = tid & 15;
    int ty = tid >> 4;
    int row0 = blockIdx.x * 64;
    int col0 = blockIdx.y * 64;

    float acc[4][4];
#pragma unroll
    for (int i = 0; i < 4; i++)
#pragma unroll
        for (int j = 0; j < 4; j++) acc[i][j] = 0.f;

    for (int k0 = 0; k0 < K; k0 += 16) {
        for (int i = tid; i < 64 * 16; i += 256) {
            int m = i >> 4, kk = i & 15;
            int row = row0 + m;
            As[kk][m] = (row < M) ? A[(size_t)row * K + k0 + kk] : 0.f;
        }
        for (int i = tid; i < 16 * 64; i += 256) {
            int kk = i >> 6, n = i & 63;
            int col = col0 + n;
            Bs[kk][n] = (col < Nc) ? Bw[(size_t)(k0 + kk) * ldb + col] : 0.f;
        }
        __syncthreads();
#pragma unroll
        for (int kk = 0; kk < 16; ++kk) {
            float av[4], bv[4];
#pragma unroll
            for (int i = 0; i < 4; i++) av[i] = As[kk][ty * 4 + i];
#pragma unroll
            for (int j = 0; j < 4; j++) bv[j] = Bs[kk][tx * 4 + j];
#pragma unroll
            for (int i = 0; i < 4; i++)
#pragma unroll
                for (int j = 0; j < 4; j++)
                    acc[i][j] = fmaf(av[i], bv[j], acc[i][j]);
        }
        __syncthreads();
    }

#pragma unroll
    for (int i = 0; i < 4; i++) {
        int row = row0 + ty * 4 + i;
        if (row >= M) continue;
#pragma unroll
        for (int j = 0; j < 4; j++) {
            int col = col0 + tx * 4 + j;
            if (col >= Nc) continue;
            float v = acc[i][j];
            if (bias) v += bias[col];
            C[(size_t)row * ldc + ccol0 + col] = v;
        }
    }
}

// ---------------- gather: out[dst, col0+f] = (relu?)(out + dinv * sum_src g_P[src, f]) ----
// OUTS: 1=g_A, 2=g_B, 3=external
template <int OUTS>
__global__ void k_gather(float* extOut, int CF, int ldout, int col0, int relu) {
    float* out;
    if constexpr (OUTS == 1)      out = g_A;
    else if constexpr (OUTS == 2) out = g_B;
    else                          out = extOut;

    int dst = blockIdx.x;
    int b = g_rowptr[dst], t = g_rowptr[dst + 1];
    float s = g_dinv[dst];
    __shared__ int srcs[256];

    for (int f0 = 0; f0 < CF; f0 += 256) {
        int f = f0 + threadIdx.x;
        bool act = (f < CF);
        float acc = 0.f;
        for (int e0 = b; e0 < t; e0 += 256) {
            int cnt = t - e0; if (cnt > 256) cnt = 256;
            __syncthreads();
            if ((int)threadIdx.x < cnt) srcs[threadIdx.x] = g_csrc[e0 + threadIdx.x];
            __syncthreads();
            if (act) {
                for (int j = 0; j < cnt; j++)
                    acc += g_P[(size_t)srcs[j] * CF + f];
            }
        }
        if (act) {
            size_t o = (size_t)dst * ldout + col0 + f;
            float v = out[o] + s * acc;
            out[o] = relu ? fmaxf(v, 0.f) : v;
        }
    }
}

// ---------------- host orchestration ----------------
static inline int cdiv(int a, int b) { return (a + b - 1) / b; }

extern "C" void kernel_launch(void* const* d_in, const int* in_sizes, int n_in,
                              void* d_out, int out_size) {
    const float* x  = (const float*)d_in[0];
    const int*   ei = (const int*)d_in[1];   // int32! (JAX downcasts int64)
    const float* Wl1 = (const float*)d_in[2],  *Wr1 = (const float*)d_in[3],  *b1 = (const float*)d_in[4];
    const float* Wl2 = (const float*)d_in[5],  *Wr2 = (const float*)d_in[6],  *b2 = (const float*)d_in[7];
    const float* Wl3 = (const float*)d_in[8],  *Wr3 = (const float*)d_in[9],  *b3 = (const float*)d_in[10];
    const float* Wl4 = (const float*)d_in[11], *Wr4 = (const float*)d_in[12], *b4 = (const float*)d_in[13];
    const float* Wl5 = (const float*)d_in[14], *Wr5 = (const float*)d_in[15], *b5 = (const float*)d_in[16];
    float* out = (float*)d_out;
    float* h4 = out;                           // [N,256]
    float* o5 = out + (size_t)NN * 256;        // [N,5]

    // CSR build
    k_zero_int<<<cdiv(NN, 256), 256>>>();
    k_count<<<cdiv(EE, 256), 256>>>(ei);
    k_scan<<<1, 1024>>>();
    k_fill<<<cdiv(EE, 256), 256>>>(ei);
    k_sort<<<cdiv(NN, 256), 256>>>();

    const int GX = cdiv(NN, 64);

    // ---- L1: x[768] -> g_A h1[1536], chunked Fo 2x768 ----
    k_gemm<2, 1><<<dim3(GX, 24), 256>>>(x, nullptr, Wr1, b1, NN, 768, 1536, 1536, 1536, 0);
    for (int c = 0; c < 2; ++c) {
        k_gemm<2, 0><<<dim3(GX, 12), 256>>>(x, nullptr, Wl1 + c * 768, nullptr,
                                            NN, 768, 768, 1536, 768, 0);
        k_gather<1><<<NN, 256>>>(nullptr, 768, 1536, c * 768, 1);
    }

    // ---- L2: g_A h1[1536] -> g_B h2[768] ----
    k_gemm<0, 2><<<dim3(GX, 12), 256>>>(nullptr, nullptr, Wr2, b2, NN, 1536, 768, 768, 768, 0);
    k_gemm<0, 0><<<dim3(GX, 12), 256>>>(nullptr, nullptr, Wl2, nullptr, NN, 1536, 768, 768, 768, 0);
    k_gather<2><<<NN, 256>>>(nullptr, 768, 768, 0, 1);

    // ---- L3: g_B h2[768] -> g_A h3[384] ----
    k_gemm<1, 1><<<dim3(GX, 6), 256>>>(nullptr, nullptr, Wr3, b3, NN, 768, 384, 384, 384, 0);
    k_gemm<1, 0><<<dim3(GX, 6), 256>>>(nullptr, nullptr, Wl3, nullptr, NN, 768, 384, 384, 384, 0);
    k_gather<1><<<NN, 256>>>(nullptr, 384, 384, 0, 1);

    // ---- L4: g_A h3[384] -> d_out h4[256] ----
    k_gemm<0, 3><<<dim3(GX, 4), 256>>>(nullptr, h4, Wr4, b4, NN, 384, 256, 256, 256, 0);
    k_gemm<0, 0><<<dim3(GX, 4), 256>>>(nullptr, nullptr, Wl4, nullptr, NN, 384, 256, 256, 256, 0);
    k_gather<3><<<NN, 256>>>(h4, 256, 256, 0, 1);

    // ---- L5: d_out h4[256] -> d_out o5[5], no relu ----
    k_gemm<2, 3><<<dim3(GX, 1), 256>>>(h4, o5, Wr5, b5, NN, 256, 5, 5, 5, 0);
    k_gemm<2, 0><<<dim3(GX, 1), 256>>>(h4, nullptr, Wl5, nullptr, NN, 256, 5, 5, 5, 0);
    k_gather<3><<<NN, 256>>>(o5, 5, 5, 0, 0);
}

// round 10
// speedup vs baseline: 3.6768x; 3.6768x over previous
#include <cuda_runtime.h>
#include <cuda_bf16.h>
#include <cstdint>

// ---------------- problem constants ----------------
#define NN 20000
#define EE 320000
// L1: 768->1536, L2: 1536->768, L3: 768->384, L4: 384->256, L5: 256->5

// ---------------- scratch (device globals) ----------------
__device__ float g_P[(size_t)NN * 1536];   // pre-aggregation linear output
__device__ float g_A[(size_t)NN * 1536];   // activation ping (h1 / h3)
__device__ float g_B[(size_t)NN * 768];    // activation pong (h2)
__device__ __nv_bfloat16 g_Ahi[(size_t)NN * 1536];
__device__ __nv_bfloat16 g_Alo[(size_t)NN * 1536];
#define WSZ 5505024
__device__ __nv_bfloat16 g_Whi[WSZ];       // transposed [N,K] weight splits
__device__ __nv_bfloat16 g_Wlo[WSZ];
__device__ float g_dinv[NN];
__device__ int   g_deg[NN];
__device__ int   g_rowptr[NN + 1];
__device__ int   g_cursor[NN];
__device__ int   g_csrc[EE];

// ---------------- small PTX helpers (family-portable only) ----------------
__device__ __forceinline__ uint32_t smem_u32(const void* p) {
    uint32_t a;
    asm("{ .reg .u64 t; cvta.to.shared.u64 t, %1; cvt.u32.u64 %0, t; }" : "=r"(a) : "l"(p));
    return a;
}
__device__ __forceinline__ void ldsm4(uint32_t* r, uint32_t addr) {
    asm volatile("ldmatrix.sync.aligned.m8n8.x4.shared.b16 {%0,%1,%2,%3}, [%4];"
                 : "=r"(r[0]), "=r"(r[1]), "=r"(r[2]), "=r"(r[3]) : "r"(addr));
}
__device__ __forceinline__ void ldsm2(uint32_t* r, uint32_t addr) {
    asm volatile("ldmatrix.sync.aligned.m8n8.x2.shared.b16 {%0,%1}, [%2];"
                 : "=r"(r[0]), "=r"(r[1]) : "r"(addr));
}
__device__ __forceinline__ void mma_bf16(float* c, const uint32_t* a, const uint32_t* b) {
    asm volatile(
        "mma.sync.aligned.m16n8k16.row.col.f32.bf16.bf16.f32 "
        "{%0,%1,%2,%3}, {%4,%5,%6,%7}, {%8,%9}, {%0,%1,%2,%3};"
        : "+f"(c[0]), "+f"(c[1]), "+f"(c[2]), "+f"(c[3])
        : "r"(a[0]), "r"(a[1]), "r"(a[2]), "r"(a[3]), "r"(b[0]), "r"(b[1]));
}

// ---------------- CSR build ----------------
__global__ void k_zero_int() {
    int i = blockIdx.x * blockDim.x + threadIdx.x;
    if (i < NN) { g_deg[i] = 0; g_cursor[i] = 0; }
}
__global__ void k_count(const int* __restrict__ ei) {
    int e = blockIdx.x * blockDim.x + threadIdx.x;
    if (e < EE) atomicAdd(&g_deg[ei[EE + e]], 1);
}
__global__ void k_scan() {
    __shared__ int sh[1024];
    int tid = threadIdx.x;
    int lo = tid * 20, hi = lo + 20;
    if (hi > NN) hi = NN;
    if (lo > NN) lo = NN;
    int s = 0;
    for (int i = lo; i < hi; i++) s += g_deg[i];
    sh[tid] = s;
    __syncthreads();
    for (int off = 1; off < 1024; off <<= 1) {
        int v = (tid >= off) ? sh[tid - off] : 0;
        __syncthreads();
        sh[tid] += v;
        __syncthreads();
    }
    int run = (tid > 0) ? sh[tid - 1] : 0;
    for (int i = lo; i < hi; i++) {
        g_rowptr[i] = run;
        int d = g_deg[i];
        run += d;
        g_dinv[i] = 1.0f / fmaxf((float)d, 1.0f);
    }
    if (tid == 0) g_rowptr[NN] = EE;
}
__global__ void k_fill(const int* __restrict__ ei) {
    int e = blockIdx.x * blockDim.x + threadIdx.x;
    if (e < EE) {
        int dst = ei[EE + e];
        int pos = atomicAdd(&g_cursor[dst], 1);
        g_csrc[g_rowptr[dst] + pos] = ei[e];
    }
}
__global__ void k_sort() {
    int n = blockIdx.x * blockDim.x + threadIdx.x;
    if (n >= NN) return;
    int b = g_rowptr[n], t = g_rowptr[n + 1];
    for (int i = b + 1; i < t; i++) {
        int v = g_csrc[i];
        int j = i - 1;
        while (j >= b && g_csrc[j] > v) { g_csrc[j + 1] = g_csrc[j]; j--; }
        g_csrc[j + 1] = v;
    }
}

// ---------------- fp32 -> bf16 hi/lo splits ----------------
// INS: 0=g_A, 1=g_B, 2=external
template <int INS>
__global__ void k_split_act(const float* ext, size_t n) {
    const float* A;
    if constexpr (INS == 0)      A = g_A;
    else if constexpr (INS == 1) A = g_B;
    else                         A = ext;
    size_t i = (size_t)blockIdx.x * blockDim.x + threadIdx.x;
    if (i < n) {
        float v = A[i];
        __nv_bfloat16 h = __float2bfloat16(v);
        g_Ahi[i] = h;
        g_Alo[i] = __float2bfloat16(v - __bfloat162float(h));
    }
}
// W [K,N] row-major -> transposed splits at g_Whi/g_Wlo[woff + n*K + k]
__global__ void k_split_w(const float* __restrict__ W, int K, int N, size_t woff) {
    size_t i = (size_t)blockIdx.x * blockDim.x + threadIdx.x;
    if (i < (size_t)K * N) {
        int k = (int)(i / N), n = (int)(i % N);
        float v = W[i];
        __nv_bfloat16 h = __float2bfloat16(v);
        size_t o = woff + (size_t)n * K + k;
        g_Whi[o] = h;
        g_Wlo[o] = __float2bfloat16(v - __bfloat162float(h));
    }
}

// ---------------- mma.sync split-bf16 GEMM: C = A[M,K] @ W^T (W stored [N,K]) ----------
// Block 128x128, BK=32, 8 warps, warp tile 64x32.
// OUTS: 0=g_P, 1=g_A, 2=g_B, 3=external
#define LDT 40          // smem row stride in bf16 (32 data + 8 pad) = 80 bytes

template <int OUTS>
__global__ void __launch_bounds__(256, 2)
k_mmagemm(float* extC, const float* __restrict__ bias,
          size_t woff, int M, int K, int ldc, int relu) {
    float* C;
    if constexpr (OUTS == 0)      C = g_P;
    else if constexpr (OUTS == 1) C = g_A;
    else if constexpr (OUTS == 2) C = g_B;
    else                          C = extC;

    __shared__ __nv_bfloat16 sAh[128 * LDT];
    __shared__ __nv_bfloat16 sAl[128 * LDT];
    __shared__ __nv_bfloat16 sBh[128 * LDT];
    __shared__ __nv_bfloat16 sBl[128 * LDT];

    const int tid = threadIdx.x;
    const int lane = tid & 31, wid = tid >> 5;
    const int warp_m = wid & 1;       // 0..1 -> 64-row slab
    const int warp_n = wid >> 1;      // 0..3 -> 32-col slab
    const int row0 = blockIdx.x * 128, col0 = blockIdx.y * 128;

    const uint32_t aAh = smem_u32(sAh), aAl = smem_u32(sAl);
    const uint32_t aBh = smem_u32(sBh), aBl = smem_u32(sBl);

    const uint4* GAh = (const uint4*)g_Ahi;
    const uint4* GAl = (const uint4*)g_Alo;
    const uint4* GBh = (const uint4*)(g_Whi + woff);
    const uint4* GBl = (const uint4*)(g_Wlo + woff);
    const int K8 = K >> 3;   // uint4 per row

    float acc[4][4][4];      // [mt][nt][reg]
#pragma unroll
    for (int i = 0; i < 4; i++)
#pragma unroll
        for (int j = 0; j < 4; j++)
#pragma unroll
            for (int r = 0; r < 4; r++) acc[i][j][r] = 0.f;

    // ldmatrix lane addresses (byte offsets within tile, before region base)
    const int a_row = lane & 15, a_kq = lane >> 4;      // x4: 16 rows, 2 col-halves
    const int b_row = lane & 7,  b_kq = (lane >> 3) & 1; // x2: 8 rows, 2 col-halves

    for (int k0 = 0; k0 < K; k0 += 32) {
        // ---- global -> smem: 4 regions, 128x32 bf16 = 512 uint4 each ----
        const int k8 = k0 >> 3;
#pragma unroll
        for (int h = 0; h < 2; ++h) {
            int i = tid + h * 256;
            int r = i >> 2, c4 = i & 3;
            int grow = row0 + r;
            uint4 vh = {0,0,0,0}, vl = {0,0,0,0};
            if (grow < M) {
                size_t go = (size_t)grow * K8 + k8 + c4;
                vh = GAh[go];
                vl = GAl[go];
            }
            int so = r * (LDT / 8) + c4;  // uint4 units within smem (LDT=40 bf16 = 5 uint4)
            ((uint4*)sAh)[so] = vh;
            ((uint4*)sAl)[so] = vl;
            size_t gb = (size_t)(col0 + r) * K8 + k8 + c4;
            ((uint4*)sBh)[so] = GBh[gb];
            ((uint4*)sBl)[so] = GBl[gb];
        }
        __syncthreads();

        // ---- 2 x k16 steps ----
#pragma unroll
        for (int ks = 0; ks < 2; ++ks) {
            const int kk = ks * 16;
            // B frags: 4 n-tiles, hi+lo
            uint32_t bh[4][2], bl[4][2];
#pragma unroll
            for (int nt = 0; nt < 4; ++nt) {
                int n = warp_n * 32 + nt * 8 + b_row;
                uint32_t off = (uint32_t)(n * (LDT * 2) + (kk + b_kq * 8) * 2);
                ldsm2(bh[nt], aBh + off);
                ldsm2(bl[nt], aBl + off);
            }
#pragma unroll
            for (int mt = 0; mt < 4; ++mt) {
                int m = warp_m * 64 + mt * 16 + a_row;
                uint32_t off = (uint32_t)(m * (LDT * 2) + (kk + a_kq * 8) * 2);
                uint32_t ah[4], al[4];
                ldsm4(ah, aAh + off);
                ldsm4(al, aAl + off);
#pragma unroll
                for (int nt = 0; nt < 4; ++nt) {
                    mma_bf16(acc[mt][nt], ah, bh[nt]);  // hi*hi
                    mma_bf16(acc[mt][nt], ah, bl[nt]);  // hi*lo
                    mma_bf16(acc[mt][nt], al, bh[nt]);  // lo*hi
                }
            }
        }
        __syncthreads();
    }

    // ---- epilogue ----
    const int erow = lane >> 2, ecol = (lane & 3) * 2;
#pragma unroll
    for (int mt = 0; mt < 4; ++mt) {
        int mb = row0 + warp_m * 64 + mt * 16;
#pragma unroll
        for (int half = 0; half < 2; ++half) {
            int row = mb + erow + half * 8;
            if (row >= M) continue;
            float* Cr = C + (size_t)row * ldc;
#pragma unroll
            for (int nt = 0; nt < 4; ++nt) {
                int col = col0 + warp_n * 32 + nt * 8 + ecol;
                float v0 = acc[mt][nt][half * 2 + 0];
                float v1 = acc[mt][nt][half * 2 + 1];
                if (bias) { v0 += bias[col]; v1 += bias[col + 1]; }
                if (relu) { v0 = fmaxf(v0, 0.f); v1 = fmaxf(v1, 0.f); }
                Cr[col] = v0;
                Cr[col + 1] = v1;
            }
        }
    }
}

// ---------------- SIMT GEMM (kept for L5, Nc=5) ----------------
template <int INS, int OUTS>
__global__ void __launch_bounds__(256)
k_gemm(const float* extA, float* extC,
       const float* __restrict__ Bw, const float* __restrict__ bias,
       int M, int K, int Nc, int ldb, int ldc, int ccol0) {
    const float* A;
    if constexpr (INS == 0)      A = g_A;
    else if constexpr (INS == 1) A = g_B;
    else                         A = extA;
    float* C;
    if constexpr (OUTS == 0)      C = g_P;
    else if constexpr (OUTS == 1) C = g_A;
    else if constexpr (OUTS == 2) C = g_B;
    else                          C = extC;

    __shared__ float As[16][64];
    __shared__ float Bs[16][65];
    int tid = threadIdx.x;
    int tx = tid & 15, ty = tid >> 4;
    int row0 = blockIdx.x * 64, col0 = blockIdx.y * 64;

    float acc[4][4];
#pragma unroll
    for (int i = 0; i < 4; i++)
#pragma unroll
        for (int j = 0; j < 4; j++) acc[i][j] = 0.f;

    for (int k0 = 0; k0 < K; k0 += 16) {
        for (int i = tid; i < 64 * 16; i += 256) {
            int m = i >> 4, kk = i & 15;
            int row = row0 + m;
            As[kk][m] = (row < M) ? A[(size_t)row * K + k0 + kk] : 0.f;
        }
        for (int i = tid; i < 16 * 64; i += 256) {
            int kk = i >> 6, n = i & 63;
            int col = col0 + n;
            Bs[kk][n] = (col < Nc) ? Bw[(size_t)(k0 + kk) * ldb + col] : 0.f;
        }
        __syncthreads();
#pragma unroll
        for (int kk = 0; kk < 16; ++kk) {
            float av[4], bv[4];
#pragma unroll
            for (int i = 0; i < 4; i++) av[i] = As[kk][ty * 4 + i];
#pragma unroll
            for (int j = 0; j < 4; j++) bv[j] = Bs[kk][tx * 4 + j];
#pragma unroll
            for (int i = 0; i < 4; i++)
#pragma unroll
                for (int j = 0; j < 4; j++)
                    acc[i][j] = fmaf(av[i], bv[j], acc[i][j]);
        }
        __syncthreads();
    }
#pragma unroll
    for (int i = 0; i < 4; i++) {
        int row = row0 + ty * 4 + i;
        if (row >= M) continue;
#pragma unroll
        for (int j = 0; j < 4; j++) {
            int col = col0 + tx * 4 + j;
            if (col >= Nc) continue;
            float v = acc[i][j];
            if (bias) v += bias[col];
            C[(size_t)row * ldc + ccol0 + col] = v;
        }
    }
}

// ---------------- gather: out[dst, f] = (relu?)(out + dinv * sum_src g_P[src, f]) ----------
template <int OUTS>
__global__ void k_gather(float* extOut, int CF, int ldout, int col0, int relu) {
    float* out;
    if constexpr (OUTS == 1)      out = g_A;
    else if constexpr (OUTS == 2) out = g_B;
    else                          out = extOut;

    int dst = blockIdx.x;
    int b = g_rowptr[dst], t = g_rowptr[dst + 1];
    float s = g_dinv[dst];
    __shared__ int srcs[256];

    for (int f0 = 0; f0 < CF; f0 += 256) {
        int f = f0 + threadIdx.x;
        bool act = (f < CF);
        float acc = 0.f;
        for (int e0 = b; e0 < t; e0 += 256) {
            int cnt = t - e0; if (cnt > 256) cnt = 256;
            __syncthreads();
            if ((int)threadIdx.x < cnt) srcs[threadIdx.x] = g_csrc[e0 + threadIdx.x];
            __syncthreads();
            if (act) {
                for (int j = 0; j < cnt; j++)
                    acc += g_P[(size_t)srcs[j] * CF + f];
            }
        }
        if (act) {
            size_t o = (size_t)dst * ldout + col0 + f;
            float v = out[o] + s * acc;
            out[o] = relu ? fmaxf(v, 0.f) : v;
        }
    }
}

// ---------------- host orchestration ----------------
static inline int cdiv(long long a, long long b) { return (int)((a + b - 1) / b); }

// weight split offsets (elements), all multiples of 8 (uint4 alignment)
#define WOFF_R1 0ull
#define WOFF_L1 1179648ull
#define WOFF_R2 2359296ull
#define WOFF_L2 3538944ull
#define WOFF_R3 4718592ull
#define WOFF_L3 5013504ull
#define WOFF_R4 5308416ull
#define WOFF_L4 5406720ull

extern "C" void kernel_launch(void* const* d_in, const int* in_sizes, int n_in,
                              void* d_out, int out_size) {
    const float* x  = (const float*)d_in[0];
    const int*   ei = (const int*)d_in[1];   // int32 (JAX downcasts int64)
    const float* Wl1 = (const float*)d_in[2],  *Wr1 = (const float*)d_in[3],  *b1 = (const float*)d_in[4];
    const float* Wl2 = (const float*)d_in[5],  *Wr2 = (const float*)d_in[6],  *b2 = (const float*)d_in[7];
    const float* Wl3 = (const float*)d_in[8],  *Wr3 = (const float*)d_in[9],  *b3 = (const float*)d_in[10];
    const float* Wl4 = (const float*)d_in[11], *Wr4 = (const float*)d_in[12], *b4 = (const float*)d_in[13];
    const float* Wl5 = (const float*)d_in[14], *Wr5 = (const float*)d_in[15], *b5 = (const float*)d_in[16];
    float* out = (float*)d_out;
    float* h4 = out;                          // [N,256]
    float* o5 = out + (size_t)NN * 256;       // [N,5]

    // CSR build
    k_zero_int<<<cdiv(NN, 256), 256>>>();
    k_count<<<cdiv(EE, 256), 256>>>(ei);
    k_scan<<<1, 1024>>>();
    k_fill<<<cdiv(EE, 256), 256>>>(ei);
    k_sort<<<cdiv(NN, 256), 256>>>();

    // weight splits (transposed, bf16 hi/lo)
    k_split_w<<<cdiv(768 * 1536, 256), 256>>>(Wr1, 768, 1536, WOFF_R1);
    k_split_w<<<cdiv(768 * 1536, 256), 256>>>(Wl1, 768, 1536, WOFF_L1);
    k_split_w<<<cdiv(1536 * 768, 256), 256>>>(Wr2, 1536, 768, WOFF_R2);
    k_split_w<<<cdiv(1536 * 768, 256), 256>>>(Wl2, 1536, 768, WOFF_L2);
    k_split_w<<<cdiv(768 * 384, 256), 256>>>(Wr3, 768, 384, WOFF_R3);
    k_split_w<<<cdiv(768 * 384, 256), 256>>>(Wl3, 768, 384, WOFF_L3);
    k_split_w<<<cdiv(384 * 256, 256), 256>>>(Wr4, 384, 256, WOFF_R4);
    k_split_w<<<cdiv(384 * 256, 256), 256>>>(Wl4, 384, 256, WOFF_L4);

    const int GX = cdiv(NN, 128);   // 157

    // ---- L1: x[768] -> g_A h1[1536] ----
    k_split_act<2><<<cdiv((long long)NN * 768, 256), 256>>>(x, (size_t)NN * 768);
    k_mmagemm<1><<<dim3(GX, 12), 256>>>(nullptr, b1, WOFF_R1, NN, 768, 1536, 0);
    k_mmagemm<0><<<dim3(GX, 12), 256>>>(nullptr, nullptr, WOFF_L1, NN, 768, 1536, 0);
    k_gather<1><<<NN, 256>>>(nullptr, 1536, 1536, 0, 1);

    // ---- L2: g_A h1[1536] -> g_B h2[768] ----
    k_split_act<0><<<cdiv((long long)NN * 1536, 256), 256>>>(nullptr, (size_t)NN * 1536);
    k_mmagemm<2><<<dim3(GX, 6), 256>>>(nullptr, b2, WOFF_R2, NN, 1536, 768, 0);
    k_mmagemm<0><<<dim3(GX, 6), 256>>>(nullptr, nullptr, WOFF_L2, NN, 1536, 768, 0);
    k_gather<2><<<NN, 256>>>(nullptr, 768, 768, 0, 1);

    // ---- L3: g_B h2[768] -> g_A h3[384] ----
    k_split_act<1><<<cdiv((long long)NN * 768, 256), 256>>>(nullptr, (size_t)NN * 768);
    k_mmagemm<1><<<dim3(GX, 3), 256>>>(nullptr, b3, WOFF_R3, NN, 768, 384, 0);
    k_mmagemm<0><<<dim3(GX, 3), 256>>>(nullptr, nullptr, WOFF_L3, NN, 768, 384, 0);
    k_gather<1><<<NN, 256>>>(nullptr, 384, 384, 0, 1);

    // ---- L4: g_A h3[384] -> d_out h4[256] ----
    k_split_act<0><<<cdiv((long long)NN * 384, 256), 256>>>(nullptr, (size_t)NN * 384);
    k_mmagemm<3><<<dim3(GX, 2), 256>>>(h4, b4, WOFF_R4, NN, 384, 256, 0);
    k_mmagemm<0><<<dim3(GX, 2), 256>>>(nullptr, nullptr, WOFF_L4, NN, 384, 256, 0);
    k_gather<3><<<NN, 256>>>(h4, 256, 256, 0, 1);

    // ---- L5: h4[256] -> o5[5] (SIMT, tiny) ----
    const int GX64 = cdiv(NN, 64);
    k_gemm<2, 3><<<dim3(GX64, 1), 256>>>(h4, o5, Wr5, b5, NN, 256, 5, 5, 5, 0);
    k_gemm<2, 0><<<dim3(GX64, 1), 256>>>(h4, nullptr, Wl5, nullptr, NN, 256, 5, 5, 5, 0);
    k_gather<3><<<NN, 256>>>(o5, 5, 5, 0, 0);
}

// round 11
// speedup vs baseline: 4.2062x; 1.1440x over previous
#include <cuda_runtime.h>
#include <cuda_bf16.h>
#include <cstdint>

// ---------------- problem constants ----------------
#define NN 20000
#define EE 320000
// L1: 768->1536, L2: 1536->768, L3: 768->384, L4: 384->256, L5: 256->5

// ---------------- scratch (device globals) ----------------
__device__ float g_P[(size_t)NN * 1536];   // pre-aggregation linear output
__device__ float g_A[(size_t)NN * 1536];   // activation ping (h1 / h3)
__device__ float g_B[(size_t)NN * 768];    // activation pong (h2)
__device__ __nv_bfloat16 g_Ahi[(size_t)NN * 1536];
__device__ __nv_bfloat16 g_Alo[(size_t)NN * 1536];
#define WSZ 5505024
__device__ __nv_bfloat16 g_Whi[WSZ];       // transposed [N,K] weight splits, [Wr;Wl] packed
__device__ __nv_bfloat16 g_Wlo[WSZ];
__device__ float g_dinv[NN];
__device__ int   g_deg[NN];
__device__ int   g_rowptr[NN + 1];
__device__ int   g_cursor[NN];
__device__ int   g_csrc[EE];

// ---------------- PTX helpers (family-portable only) ----------------
__device__ __forceinline__ uint32_t smem_u32(const void* p) {
    uint32_t a;
    asm("{ .reg .u64 t; cvta.to.shared.u64 t, %1; cvt.u32.u64 %0, t; }" : "=r"(a) : "l"(p));
    return a;
}
__device__ __forceinline__ void ldsm4(uint32_t* r, uint32_t addr) {
    asm volatile("ldmatrix.sync.aligned.m8n8.x4.shared.b16 {%0,%1,%2,%3}, [%4];"
                 : "=r"(r[0]), "=r"(r[1]), "=r"(r[2]), "=r"(r[3]) : "r"(addr));
}
__device__ __forceinline__ void ldsm2(uint32_t* r, uint32_t addr) {
    asm volatile("ldmatrix.sync.aligned.m8n8.x2.shared.b16 {%0,%1}, [%2];"
                 : "=r"(r[0]), "=r"(r[1]) : "r"(addr));
}
__device__ __forceinline__ void mma_bf16(float* c, const uint32_t* a, const uint32_t* b) {
    asm volatile(
        "mma.sync.aligned.m16n8k16.row.col.f32.bf16.bf16.f32 "
        "{%0,%1,%2,%3}, {%4,%5,%6,%7}, {%8,%9}, {%0,%1,%2,%3};"
        : "+f"(c[0]), "+f"(c[1]), "+f"(c[2]), "+f"(c[3])
        : "r"(a[0]), "r"(a[1]), "r"(a[2]), "r"(a[3]), "r"(b[0]), "r"(b[1]));
}
__device__ __forceinline__ void cp16(uint32_t saddr, const void* g, bool valid) {
    int sz = valid ? 16 : 0;
    asm volatile("cp.async.cg.shared.global [%0], [%1], 16, %2;"
                 :: "r"(saddr), "l"(g), "r"(sz));
}
#define CP_COMMIT() asm volatile("cp.async.commit_group;" ::: "memory")
#define CP_WAIT1()  asm volatile("cp.async.wait_group 1;" ::: "memory")
#define CP_WAIT0()  asm volatile("cp.async.wait_group 0;" ::: "memory")

// ---------------- CSR build ----------------
__global__ void k_zero_int() {
    int i = blockIdx.x * blockDim.x + threadIdx.x;
    if (i < NN) { g_deg[i] = 0; g_cursor[i] = 0; }
}
__global__ void k_count(const int* __restrict__ ei) {
    int e = blockIdx.x * blockDim.x + threadIdx.x;
    if (e < EE) atomicAdd(&g_deg[ei[EE + e]], 1);
}
__global__ void k_scan() {
    __shared__ int sh[1024];
    int tid = threadIdx.x;
    int lo = tid * 20, hi = lo + 20;
    if (hi > NN) hi = NN;
    if (lo > NN) lo = NN;
    int s = 0;
    for (int i = lo; i < hi; i++) s += g_deg[i];
    sh[tid] = s;
    __syncthreads();
    for (int off = 1; off < 1024; off <<= 1) {
        int v = (tid >= off) ? sh[tid - off] : 0;
        __syncthreads();
        sh[tid] += v;
        __syncthreads();
    }
    int run = (tid > 0) ? sh[tid - 1] : 0;
    for (int i = lo; i < hi; i++) {
        g_rowptr[i] = run;
        int d = g_deg[i];
        run += d;
        g_dinv[i] = 1.0f / fmaxf((float)d, 1.0f);
    }
    if (tid == 0) g_rowptr[NN] = EE;
}
__global__ void k_fill(const int* __restrict__ ei) {
    int e = blockIdx.x * blockDim.x + threadIdx.x;
    if (e < EE) {
        int dst = ei[EE + e];
        int pos = atomicAdd(&g_cursor[dst], 1);
        g_csrc[g_rowptr[dst] + pos] = ei[e];
    }
}
__global__ void k_sort() {
    int n = blockIdx.x * blockDim.x + threadIdx.x;
    if (n >= NN) return;
    int b = g_rowptr[n], t = g_rowptr[n + 1];
    for (int i = b + 1; i < t; i++) {
        int v = g_csrc[i];
        int j = i - 1;
        while (j >= b && g_csrc[j] > v) { g_csrc[j + 1] = g_csrc[j]; j--; }
        g_csrc[j + 1] = v;
    }
}

// ---------------- fp32 -> bf16 hi/lo split (external input only) ----------------
__global__ void k_split_ext(const float* __restrict__ A, size_t n) {
    size_t i = (size_t)blockIdx.x * blockDim.x + threadIdx.x;
    if (i < n) {
        float v = A[i];
        __nv_bfloat16 h = __float2bfloat16(v);
        g_Ahi[i] = h;
        g_Alo[i] = __float2bfloat16(v - __bfloat162float(h));
    }
}
// W [K,N] row-major -> transposed splits at g_Whi/g_Wlo[woff + n*K + k]
__global__ void k_split_w(const float* __restrict__ W, int K, int N, size_t woff) {
    size_t i = (size_t)blockIdx.x * blockDim.x + threadIdx.x;
    if (i < (size_t)K * N) {
        int k = (int)(i / N), n = (int)(i % N);
        float v = W[i];
        __nv_bfloat16 h = __float2bfloat16(v);
        size_t o = woff + (size_t)n * K + k;
        g_Whi[o] = h;
        g_Wlo[o] = __float2bfloat16(v - __bfloat162float(h));
    }
}

// ---------------- fused dual-output mma.sync GEMM --------------------------------
// Computes A[M,K] @ [Wr;Wl]^T (packed [Ntot=2*Fo, K]).
// Col-blocks < Fo: dest = OUTS buffer (+bias). Col-blocks >= Fo: dest = g_P.
// Block 128x128, BK=32, 8 warps, warp tile 64x32, 2-stage cp.async pipeline.
// OUTS: 1=g_A, 2=g_B, 3=external
#define LDT 40                    // smem row stride in bf16 (32 data + 8 pad) = 80 B
#define REGSZ (128 * LDT * 2)     // one region: 10240 B
#define STGSZ (4 * REGSZ)         // stage: Ah, Al, Bh, Bl = 40960 B
#define SMEM_DYN (2 * STGSZ)      // 81920 B

template <int OUTS>
__global__ void __launch_bounds__(256, 2)
k_mmagemm(float* extC, const float* __restrict__ bias,
          size_t woff, int M, int K, int Fo, int ldc1) {
    extern __shared__ __align__(16) char sdyn[];
    const uint32_t sb = smem_u32(sdyn);

    const int tid = threadIdx.x;
    const int lane = tid & 31, wid = tid >> 5;
    const int warp_m = wid & 1;       // 0..1 -> 64-row slab
    const int warp_n = wid >> 1;      // 0..3 -> 32-col slab
    const int row0 = blockIdx.x * 128, col0 = blockIdx.y * 128;

    const uint4* GAh = (const uint4*)g_Ahi;
    const uint4* GAl = (const uint4*)g_Alo;
    const uint4* GBh = (const uint4*)(g_Whi + woff);
    const uint4* GBl = (const uint4*)(g_Wlo + woff);
    const int K8 = K >> 3;   // uint4 per row
    const int niter = K >> 5;

    float acc[4][4][4];      // [mt][nt][reg]
#pragma unroll
    for (int i = 0; i < 4; i++)
#pragma unroll
        for (int j = 0; j < 4; j++)
#pragma unroll
            for (int r = 0; r < 4; r++) acc[i][j][r] = 0.f;

    // stage loader: 4 regions x 512 uint4, 8 cp.async per thread
    auto load_stage = [&](int it, int s) {
        const int k8 = it << 2;
        const uint32_t base = sb + s * STGSZ;
#pragma unroll
        for (int h = 0; h < 2; ++h) {
            int i = tid + h * 256;
            int r = i >> 2, c4 = i & 3;
            uint32_t so = base + (uint32_t)(r * 5 + c4) * 16;
            int grow = row0 + r;
            bool v = grow < M;
            size_t go = v ? ((size_t)grow * K8 + k8 + c4) : 0;
            cp16(so,             GAh + go, v);
            cp16(so + REGSZ,     GAl + go, v);
            size_t gb = (size_t)(col0 + r) * K8 + k8 + c4;
            cp16(so + 2 * REGSZ, GBh + gb, true);
            cp16(so + 3 * REGSZ, GBl + gb, true);
        }
    };

    // ldmatrix lane addressing
    const int a_row = lane & 15, a_kq = lane >> 4;       // x4: 16 rows, 2 col-halves
    const int b_row = lane & 7,  b_kq = (lane >> 3) & 1; // x2: 8 rows, 2 col-halves

    load_stage(0, 0);
    CP_COMMIT();

    for (int it = 0; it < niter; ++it) {
        const int s = it & 1;
        if (it + 1 < niter) {
            load_stage(it + 1, s ^ 1);
            CP_COMMIT();
            CP_WAIT1();
        } else {
            CP_WAIT0();
        }
        __syncthreads();

        const uint32_t aAh = sb + s * STGSZ;
        const uint32_t aAl = aAh + REGSZ;
        const uint32_t aBh = aAh + 2 * REGSZ;
        const uint32_t aBl = aAh + 3 * REGSZ;

#pragma unroll
        for (int ks = 0; ks < 2; ++ks) {
            const int kk = ks * 16;
            uint32_t bh[4][2], bl[4][2];
#pragma unroll
            for (int nt = 0; nt < 4; ++nt) {
                int n = warp_n * 32 + nt * 8 + b_row;
                uint32_t off = (uint32_t)(n * (LDT * 2) + (kk + b_kq * 8) * 2);
                ldsm2(bh[nt], aBh + off);
                ldsm2(bl[nt], aBl + off);
            }
#pragma unroll
            for (int mt = 0; mt < 4; ++mt) {
                int m = warp_m * 64 + mt * 16 + a_row;
                uint32_t off = (uint32_t)(m * (LDT * 2) + (kk + a_kq * 8) * 2);
                uint32_t ah[4], al[4];
                ldsm4(ah, aAh + off);
                ldsm4(al, aAl + off);
#pragma unroll
                for (int nt = 0; nt < 4; ++nt) {
                    mma_bf16(acc[mt][nt], ah, bh[nt]);  // hi*hi
                    mma_bf16(acc[mt][nt], ah, bl[nt]);  // hi*lo
                    mma_bf16(acc[mt][nt], al, bh[nt]);  // lo*hi
                }
            }
        }
        __syncthreads();
    }

    // ---- epilogue with dual routing ----
    const bool isP = (col0 >= Fo);
    float* C;
    int ldc, colb;
    if (isP) {
        C = g_P; ldc = Fo; colb = col0 - Fo;
    } else {
        if constexpr (OUTS == 1)      C = g_A;
        else if constexpr (OUTS == 2) C = g_B;
        else                          C = extC;
        ldc = ldc1; colb = col0;
    }
    const int erow = lane >> 2, ecol = (lane & 3) * 2;
#pragma unroll
    for (int mt = 0; mt < 4; ++mt) {
        int mb = row0 + warp_m * 64 + mt * 16;
#pragma unroll
        for (int half = 0; half < 2; ++half) {
            int row = mb + erow + half * 8;
            if (row >= M) continue;
            float* Cr = C + (size_t)row * ldc;
#pragma unroll
            for (int nt = 0; nt < 4; ++nt) {
                int col = colb + warp_n * 32 + nt * 8 + ecol;
                float v0 = acc[mt][nt][half * 2 + 0];
                float v1 = acc[mt][nt][half * 2 + 1];
                if (!isP && bias) { v0 += bias[col]; v1 += bias[col + 1]; }
                Cr[col] = v0;
                Cr[col + 1] = v1;
            }
        }
    }
}

// ---------------- SIMT GEMM (kept for L5, Nc=5) ----------------
template <int INS, int OUTS>
__global__ void __launch_bounds__(256)
k_gemm(const float* extA, float* extC,
       const float* __restrict__ Bw, const float* __restrict__ bias,
       int M, int K, int Nc, int ldb, int ldc, int ccol0) {
    const float* A;
    if constexpr (INS == 0)      A = g_A;
    else if constexpr (INS == 1) A = g_B;
    else                         A = extA;
    float* C;
    if constexpr (OUTS == 0)      C = g_P;
    else if constexpr (OUTS == 1) C = g_A;
    else if constexpr (OUTS == 2) C = g_B;
    else                          C = extC;

    __shared__ float As[16][64];
    __shared__ float Bs[16][65];
    int tid = threadIdx.x;
    int tx = tid & 15, ty = tid >> 4;
    int row0 = blockIdx.x * 64, col0 = blockIdx.y * 64;

    float acc[4][4];
#pragma unroll
    for (int i = 0; i < 4; i++)
#pragma unroll
        for (int j = 0; j < 4; j++) acc[i][j] = 0.f;

    for (int k0 = 0; k0 < K; k0 += 16) {
        for (int i = tid; i < 64 * 16; i += 256) {
            int m = i >> 4, kk = i & 15;
            int row = row0 + m;
            As[kk][m] = (row < M) ? A[(size_t)row * K + k0 + kk] : 0.f;
        }
        for (int i = tid; i < 16 * 64; i += 256) {
            int kk = i >> 6, n = i & 63;
            int col = col0 + n;
            Bs[kk][n] = (col < Nc) ? Bw[(size_t)(k0 + kk) * ldb + col] : 0.f;
        }
        __syncthreads();
#pragma unroll
        for (int kk = 0; kk < 16; ++kk) {
            float av[4], bv[4];
#pragma unroll
            for (int i = 0; i < 4; i++) av[i] = As[kk][ty * 4 + i];
#pragma unroll
            for (int j = 0; j < 4; j++) bv[j] = Bs[kk][tx * 4 + j];
#pragma unroll
            for (int i = 0; i < 4; i++)
#pragma unroll
                for (int j = 0; j < 4; j++)
                    acc[i][j] = fmaf(av[i], bv[j], acc[i][j]);
        }
        __syncthreads();
    }
#pragma unroll
    for (int i = 0; i < 4; i++) {
        int row = row0 + ty * 4 + i;
        if (row >= M) continue;
#pragma unroll
        for (int j = 0; j < 4; j++) {
            int col = col0 + tx * 4 + j;
            if (col >= Nc) continue;
            float v = acc[i][j];
            if (bias) v += bias[col];
            C[(size_t)row * ldc + ccol0 + col] = v;
        }
    }
}

// ---------------- gather (+ optional fused bf16 split of the result) ----------------
// out[dst, f] = (relu?)(out + dinv * sum_src g_P[src, f]); if SPLIT, also write hi/lo
// OUTS: 1=g_A, 2=g_B, 3=external
template <int OUTS, int SPLIT>
__global__ void k_gather(float* extOut, int CF, int relu) {
    float* out;
    if constexpr (OUTS == 1)      out = g_A;
    else if constexpr (OUTS == 2) out = g_B;
    else                          out = extOut;

    int dst = blockIdx.x;
    int b = g_rowptr[dst], t = g_rowptr[dst + 1];
    float s = g_dinv[dst];
    __shared__ int srcs[256];

    for (int f0 = 0; f0 < CF; f0 += 256) {
        int f = f0 + threadIdx.x;
        bool act = (f < CF);
        float acc = 0.f;
        for (int e0 = b; e0 < t; e0 += 256) {
            int cnt = t - e0; if (cnt > 256) cnt = 256;
            __syncthreads();
            if ((int)threadIdx.x < cnt) srcs[threadIdx.x] = g_csrc[e0 + threadIdx.x];
            __syncthreads();
            if (act) {
                for (int j = 0; j < cnt; j++)
                    acc += g_P[(size_t)srcs[j] * CF + f];
            }
        }
        if (act) {
            size_t o = (size_t)dst * CF + f;
            float v = out[o] + s * acc;
            if (relu) v = fmaxf(v, 0.f);
            out[o] = v;
            if constexpr (SPLIT) {
                __nv_bfloat16 h = __float2bfloat16(v);
                g_Ahi[o] = h;
                g_Alo[o] = __float2bfloat16(v - __bfloat162float(h));
            }
        }
    }
}

// ---------------- host orchestration ----------------
static inline int cdiv(long long a, long long b) { return (int)((a + b - 1) / b); }

// weight split offsets (elements); [Wr;Wl] packed per layer
#define WOFF_R1 0ull
#define WOFF_L1 1179648ull
#define WOFF_R2 2359296ull
#define WOFF_L2 3538944ull
#define WOFF_R3 4718592ull
#define WOFF_L3 5013504ull
#define WOFF_R4 5308416ull
#define WOFF_L4 5406720ull

extern "C" void kernel_launch(void* const* d_in, const int* in_sizes, int n_in,
                              void* d_out, int out_size) {
    const float* x  = (const float*)d_in[0];
    const int*   ei = (const int*)d_in[1];   // int32 (JAX downcasts int64)
    const float* Wl1 = (const float*)d_in[2],  *Wr1 = (const float*)d_in[3],  *b1 = (const float*)d_in[4];
    const float* Wl2 = (const float*)d_in[5],  *Wr2 = (const float*)d_in[6],  *b2 = (const float*)d_in[7];
    const float* Wl3 = (const float*)d_in[8],  *Wr3 = (const float*)d_in[9],  *b3 = (const float*)d_in[10];
    const float* Wl4 = (const float*)d_in[11], *Wr4 = (const float*)d_in[12], *b4 = (const float*)d_in[13];
    const float* Wl5 = (const float*)d_in[14], *Wr5 = (const float*)d_in[15], *b5 = (const float*)d_in[16];
    float* out = (float*)d_out;
    float* h4 = out;                          // [N,256]
    float* o5 = out + (size_t)NN * 256;       // [N,5]

    static bool attr_done = false;
    if (!attr_done) {
        cudaFuncSetAttribute(k_mmagemm<1>, cudaFuncAttributeMaxDynamicSharedMemorySize, SMEM_DYN);
        cudaFuncSetAttribute(k_mmagemm<2>, cudaFuncAttributeMaxDynamicSharedMemorySize, SMEM_DYN);
        cudaFuncSetAttribute(k_mmagemm<3>, cudaFuncAttributeMaxDynamicSharedMemorySize, SMEM_DYN);
        attr_done = true;
    }

    // CSR build
    k_zero_int<<<cdiv(NN, 256), 256>>>();
    k_count<<<cdiv(EE, 256), 256>>>(ei);
    k_scan<<<1, 1024>>>();
    k_fill<<<cdiv(EE, 256), 256>>>(ei);
    k_sort<<<cdiv(NN, 256), 256>>>();

    // weight splits (transposed, bf16 hi/lo)
    k_split_w<<<cdiv(768 * 1536, 256), 256>>>(Wr1, 768, 1536, WOFF_R1);
    k_split_w<<<cdiv(768 * 1536, 256), 256>>>(Wl1, 768, 1536, WOFF_L1);
    k_split_w<<<cdiv(1536 * 768, 256), 256>>>(Wr2, 1536, 768, WOFF_R2);
    k_split_w<<<cdiv(1536 * 768, 256), 256>>>(Wl2, 1536, 768, WOFF_L2);
    k_split_w<<<cdiv(768 * 384, 256), 256>>>(Wr3, 768, 384, WOFF_R3);
    k_split_w<<<cdiv(768 * 384, 256), 256>>>(Wl3, 768, 384, WOFF_L3);
    k_split_w<<<cdiv(384 * 256, 256), 256>>>(Wr4, 384, 256, WOFF_R4);
    k_split_w<<<cdiv(384 * 256, 256), 256>>>(Wl4, 384, 256, WOFF_L4);

    const int GX = cdiv(NN, 128);   // 157

    // ---- L1: x[768] -> g_A h1[1536] (fused Wr+Wl GEMM, Ntot=3072) ----
    k_split_ext<<<cdiv((long long)NN * 768, 256), 256>>>(x, (size_t)NN * 768);
    k_mmagemm<1><<<dim3(GX, 24), 256, SMEM_DYN>>>(nullptr, b1, WOFF_R1, NN, 768, 1536, 1536);
    k_gather<1, 1><<<NN, 256>>>(nullptr, 1536, 1);

    // ---- L2: g_A h1[1536] -> g_B h2[768] (Ntot=1536) ----
    k_mmagemm<2><<<dim3(GX, 12), 256, SMEM_DYN>>>(nullptr, b2, WOFF_R2, NN, 1536, 768, 768);
    k_gather<2, 1><<<NN, 256>>>(nullptr, 768, 1);

    // ---- L3: g_B h2[768] -> g_A h3[384] (Ntot=768) ----
    k_mmagemm<1><<<dim3(GX, 6), 256, SMEM_DYN>>>(nullptr, b3, WOFF_R3, NN, 768, 384, 384);
    k_gather<1, 1><<<NN, 256>>>(nullptr, 384, 1);

    // ---- L4: g_A h3[384] -> d_out h4[256] (Ntot=512) ----
    k_mmagemm<3><<<dim3(GX, 4), 256, SMEM_DYN>>>(h4, b4, WOFF_R4, NN, 384, 256, 256);
    k_gather<3, 0><<<NN, 256>>>(h4, 256, 1);

    // ---- L5: h4[256] -> o5[5] (SIMT, tiny) ----
    const int GX64 = cdiv(NN, 64);
    k_gemm<2, 3><<<dim3(GX64, 1), 256>>>(h4, o5, Wr5, b5, NN, 256, 5, 5, 5, 0);
    k_gemm<2, 0><<<dim3(GX64, 1), 256>>>(h4, nullptr, Wl5, nullptr, NN, 256, 5, 5, 5, 0);
    k_gather<3, 0><<<NN, 256>>>(o5, 5, 0);
}

// round 13
// speedup vs baseline: 5.3765x; 1.2782x over previous
#include <cuda_runtime.h>
#include <cuda_bf16.h>
#include <cuda_fp16.h>
#include <cstdint>

// ---------------- problem constants ----------------
#define NN 20000
#define EE 320000
// L1: 768->1536, L2: 1536->768, L3: 768->384, L4: 384->256, L5: 256->5

// ---------------- scratch (device globals) ----------------
__device__ float g_P[(size_t)NN * 1536];   // pre-aggregation linear output
__device__ float g_A[(size_t)NN * 1536];   // activation ping (h1 / h3)
__device__ float g_B[(size_t)NN * 768];    // activation pong (h2)
__device__ __half g_Ahi[(size_t)NN * 1536];  // fp16 split of current activations
__device__ __half g_Alo[(size_t)NN * 1536];
#define WSZ 5505024
__device__ __half g_Wh[WSZ];               // transposed [N,K] fp16 weights, [Wr;Wl] packed
__device__ float g_dinv[NN];
__device__ int   g_deg[NN];
__device__ int   g_rowptr[NN + 1];
__device__ int   g_cursor[NN];
__device__ int   g_csrc[EE];

// ---------------- PTX helpers (family-portable only) ----------------
__device__ __forceinline__ uint32_t smem_u32(const void* p) {
    uint32_t a;
    asm("{ .reg .u64 t; cvta.to.shared.u64 t, %1; cvt.u32.u64 %0, t; }" : "=r"(a) : "l"(p));
    return a;
}
__device__ __forceinline__ void ldsm4(uint32_t* r, uint32_t addr) {
    asm volatile("ldmatrix.sync.aligned.m8n8.x4.shared.b16 {%0,%1,%2,%3}, [%4];"
                 : "=r"(r[0]), "=r"(r[1]), "=r"(r[2]), "=r"(r[3]) : "r"(addr));
}
__device__ __forceinline__ void ldsm2(uint32_t* r, uint32_t addr) {
    asm volatile("ldmatrix.sync.aligned.m8n8.x2.shared.b16 {%0,%1}, [%2];"
                 : "=r"(r[0]), "=r"(r[1]) : "r"(addr));
}
__device__ __forceinline__ void mma_f16(float* c, const uint32_t* a, const uint32_t* b) {
    asm volatile(
        "mma.sync.aligned.m16n8k16.row.col.f32.f16.f16.f32 "
        "{%0,%1,%2,%3}, {%4,%5,%6,%7}, {%8,%9}, {%0,%1,%2,%3};"
        : "+f"(c[0]), "+f"(c[1]), "+f"(c[2]), "+f"(c[3])
        : "r"(a[0]), "r"(a[1]), "r"(a[2]), "r"(a[3]), "r"(b[0]), "r"(b[1]));
}
__device__ __forceinline__ void cp16(uint32_t saddr, const void* g, bool valid) {
    int sz = valid ? 16 : 0;
    asm volatile("cp.async.cg.shared.global [%0], [%1], 16, %2;"
                 :: "r"(saddr), "l"(g), "r"(sz));
}
#define CP_COMMIT() asm volatile("cp.async.commit_group;" ::: "memory")
#define CP_WAIT1()  asm volatile("cp.async.wait_group 1;" ::: "memory")
#define CP_WAIT0()  asm volatile("cp.async.wait_group 0;" ::: "memory")

// ---------------- CSR build ----------------
__global__ void k_zero_int() {
    int i = blockIdx.x * blockDim.x + threadIdx.x;
    if (i < NN) { g_deg[i] = 0; g_cursor[i] = 0; }
}
__global__ void k_count(const int* __restrict__ ei) {
    int e = blockIdx.x * blockDim.x + threadIdx.x;
    if (e < EE) atomicAdd(&g_deg[ei[EE + e]], 1);
}
__global__ void k_scan() {
    __shared__ int sh[1024];
    int tid = threadIdx.x;
    int lo = tid * 20, hi = lo + 20;
    if (hi > NN) hi = NN;
    if (lo > NN) lo = NN;
    int s = 0;
    for (int i = lo; i < hi; i++) s += g_deg[i];
    sh[tid] = s;
    __syncthreads();
    for (int off = 1; off < 1024; off <<= 1) {
        int v = (tid >= off) ? sh[tid - off] : 0;
        __syncthreads();
        sh[tid] += v;
        __syncthreads();
    }
    int run = (tid > 0) ? sh[tid - 1] : 0;
    for (int i = lo; i < hi; i++) {
        g_rowptr[i] = run;
        int d = g_deg[i];
        run += d;
        g_dinv[i] = 1.0f / fmaxf((float)d, 1.0f);
    }
    if (tid == 0) g_rowptr[NN] = EE;
}
__global__ void k_fill(const int* __restrict__ ei) {
    int e = blockIdx.x * blockDim.x + threadIdx.x;
    if (e < EE) {
        int dst = ei[EE + e];
        int pos = atomicAdd(&g_cursor[dst], 1);
        g_csrc[g_rowptr[dst] + pos] = ei[e];
    }
}
__global__ void k_sort() {
    int n = blockIdx.x * blockDim.x + threadIdx.x;
    if (n >= NN) return;
    int b = g_rowptr[n], t = g_rowptr[n + 1];
    for (int i = b + 1; i < t; i++) {
        int v = g_csrc[i];
        int j = i - 1;
        while (j >= b && g_csrc[j] > v) { g_csrc[j + 1] = g_csrc[j]; j--; }
        g_csrc[j + 1] = v;
    }
}

// ---------------- fp32 -> fp16 hi/lo split (external input only) ----------------
__global__ void k_split_ext(const float* __restrict__ A, size_t n) {
    size_t i = (size_t)blockIdx.x * blockDim.x + threadIdx.x;
    if (i < n) {
        float v = A[i];
        __half h = __float2half(v);
        g_Ahi[i] = h;
        g_Alo[i] = __float2half(v - __half2float(h));
    }
}
// W [K,N] row-major -> transposed fp16 at g_Wh[woff + n*K + k]
__global__ void k_split_w(const float* __restrict__ W, int K, int N, size_t woff) {
    size_t i = (size_t)blockIdx.x * blockDim.x + threadIdx.x;
    if (i < (size_t)K * N) {
        int k = (int)(i / N), n = (int)(i % N);
        g_Wh[woff + (size_t)n * K + k] = __float2half(W[i]);
    }
}

// ---------------- fused dual-output mma.sync GEMM (fp16, 2-product) ---------------
// Computes A[M,K] @ [Wr;Wl]^T (packed [Ntot=2*Fo, K]).
// Col-blocks < Fo: dest = OUTS buffer (+bias). Col-blocks >= Fo: dest = g_P.
// Block 128x128, BK=32, 8 warps, warp tile 64x32, 2-stage cp.async pipeline.
// OUTS: 1=g_A, 2=g_B, 3=external
#define LDT 40                    // smem row stride in halves (32 data + 8 pad) = 80 B
#define REGSZ (128 * LDT * 2)     // one region: 10240 B
#define STGSZ (3 * REGSZ)         // stage: Ah, Al, Bh = 30720 B
#define SMEM_DYN (2 * STGSZ)      // 61440 B

template <int OUTS>
__global__ void __launch_bounds__(256, 2)
k_mmagemm(float* extC, const float* __restrict__ bias,
          size_t woff, int M, int K, int Fo, int ldc1) {
    extern __shared__ __align__(16) char sdyn[];
    const uint32_t sb = smem_u32(sdyn);

    const int tid = threadIdx.x;
    const int lane = tid & 31, wid = tid >> 5;
    const int warp_m = wid & 1;       // 0..1 -> 64-row slab
    const int warp_n = wid >> 1;      // 0..3 -> 32-col slab
    const int row0 = blockIdx.x * 128, col0 = blockIdx.y * 128;

    const uint4* GAh = (const uint4*)g_Ahi;
    const uint4* GAl = (const uint4*)g_Alo;
    const uint4* GBh = (const uint4*)(g_Wh + woff);
    const int K8 = K >> 3;   // uint4 per row
    const int niter = K >> 5;

    float acc[4][4][4];      // [mt][nt][reg]
#pragma unroll
    for (int i = 0; i < 4; i++)
#pragma unroll
        for (int j = 0; j < 4; j++)
#pragma unroll
            for (int r = 0; r < 4; r++) acc[i][j][r] = 0.f;

    // stage loader: 3 regions x 512 uint4, 6 cp.async per thread
    auto load_stage = [&](int it, int s) {
        const int k8 = it << 2;
        const uint32_t base = sb + s * STGSZ;
#pragma unroll
        for (int h = 0; h < 2; ++h) {
            int i = tid + h * 256;
            int r = i >> 2, c4 = i & 3;
            uint32_t so = base + (uint32_t)(r * 5 + c4) * 16;
            int grow = row0 + r;
            bool v = grow < M;
            size_t go = v ? ((size_t)grow * K8 + k8 + c4) : 0;
            cp16(so,             GAh + go, v);
            cp16(so + REGSZ,     GAl + go, v);
            size_t gb = (size_t)(col0 + r) * K8 + k8 + c4;
            cp16(so + 2 * REGSZ, GBh + gb, true);
        }
    };

    // ldmatrix lane addressing
    const int a_row = lane & 15, a_kq = lane >> 4;       // x4: 16 rows, 2 col-halves
    const int b_row = lane & 7,  b_kq = (lane >> 3) & 1; // x2: 8 rows, 2 col-halves

    load_stage(0, 0);
    CP_COMMIT();

    for (int it = 0; it < niter; ++it) {
        const int s = it & 1;
        if (it + 1 < niter) {
            load_stage(it + 1, s ^ 1);
            CP_COMMIT();
            CP_WAIT1();
        } else {
            CP_WAIT0();
        }
        __syncthreads();

        const uint32_t aAh = sb + s * STGSZ;
        const uint32_t aAl = aAh + REGSZ;
        const uint32_t aBh = aAh + 2 * REGSZ;

#pragma unroll
        for (int ks = 0; ks < 2; ++ks) {
            const int kk = ks * 16;
            uint32_t bh[4][2];
#pragma unroll
            for (int nt = 0; nt < 4; ++nt) {
                int n = warp_n * 32 + nt * 8 + b_row;
                uint32_t off = (uint32_t)(n * (LDT * 2) + (kk + b_kq * 8) * 2);
                ldsm2(bh[nt], aBh + off);
            }
#pragma unroll
            for (int mt = 0; mt < 4; ++mt) {
                int m = warp_m * 64 + mt * 16 + a_row;
                uint32_t off = (uint32_t)(m * (LDT * 2) + (kk + a_kq * 8) * 2);
                uint32_t ah[4], al[4];
                ldsm4(ah, aAh + off);
                ldsm4(al, aAl + off);
#pragma unroll
                for (int nt = 0; nt < 4; ++nt) {
                    mma_f16(acc[mt][nt], ah, bh[nt]);  // Ahi @ Bhi
                    mma_f16(acc[mt][nt], al, bh[nt]);  // Alo @ Bhi
                }
            }
        }
        __syncthreads();
    }

    // ---- epilogue with dual routing ----
    const bool isP = (col0 >= Fo);
    float* C;
    int ldc, colb;
    if (isP) {
        C = g_P; ldc = Fo; colb = col0 - Fo;
    } else {
        if constexpr (OUTS == 1)      C = g_A;
        else if constexpr (OUTS == 2) C = g_B;
        else                          C = extC;
        ldc = ldc1; colb = col0;
    }
    const int erow = lane >> 2, ecol = (lane & 3) * 2;
#pragma unroll
    for (int mt = 0; mt < 4; ++mt) {
        int mb = row0 + warp_m * 64 + mt * 16;
#pragma unroll
        for (int half = 0; half < 2; ++half) {
            int row = mb + erow + half * 8;
            if (row >= M) continue;
            float* Cr = C + (size_t)row * ldc;
#pragma unroll
            for (int nt = 0; nt < 4; ++nt) {
                int col = colb + warp_n * 32 + nt * 8 + ecol;
                float v0 = acc[mt][nt][half * 2 + 0];
                float v1 = acc[mt][nt][half * 2 + 1];
                if (!isP && bias) { v0 += bias[col]; v1 += bias[col + 1]; }
                Cr[col] = v0;
                Cr[col + 1] = v1;
            }
        }
    }
}

// ---------------- SIMT GEMM (kept for L5, Nc=5) ----------------
template <int INS, int OUTS>
__global__ void __launch_bounds__(256)
k_gemm(const float* extA, float* extC,
       const float* __restrict__ Bw, const float* __restrict__ bias,
       int M, int K, int Nc, int ldb, int ldc, int ccol0) {
    const float* A;
    if constexpr (INS == 0)      A = g_A;
    else if constexpr (INS == 1) A = g_B;
    else                         A = extA;
    float* C;
    if constexpr (OUTS == 0)      C = g_P;
    else if constexpr (OUTS == 1) C = g_A;
    else if constexpr (OUTS == 2) C = g_B;
    else                          C = extC;

    __shared__ float As[16][64];
    __shared__ float Bs[16][65];
    int tid = threadIdx.x;
    int tx = tid & 15, ty = tid >> 4;
    int row0 = blockIdx.x * 64, col0 = blockIdx.y * 64;

    float acc[4][4];
#pragma unroll
    for (int i = 0; i < 4; i++)
#pragma unroll
        for (int j = 0; j < 4; j++) acc[i][j] = 0.f;

    for (int k0 = 0; k0 < K; k0 += 16) {
        for (int i = tid; i < 64 * 16; i += 256) {
            int m = i >> 4, kk = i & 15;
            int row = row0 + m;
            As[kk][m] = (row < M) ? A[(size_t)row * K + k0 + kk] : 0.f;
        }
        for (int i = tid; i < 16 * 64; i += 256) {
            int kk = i >> 6, n = i & 63;
            int col = col0 + n;
            Bs[kk][n] = (col < Nc) ? Bw[(size_t)(k0 + kk) * ldb + col] : 0.f;
        }
        __syncthreads();
#pragma unroll
        for (int kk = 0; kk < 16; ++kk) {
            float av[4], bv[4];
#pragma unroll
            for (int i = 0; i < 4; i++) av[i] = As[kk][ty * 4 + i];
#pragma unroll
            for (int j = 0; j < 4; j++) bv[j] = Bs[kk][tx * 4 + j];
#pragma unroll
            for (int i = 0; i < 4; i++)
#pragma unroll
                for (int j = 0; j < 4; j++)
                    acc[i][j] = fmaf(av[i], bv[j], acc[i][j]);
        }
        __syncthreads();
    }
#pragma unroll
    for (int i = 0; i < 4; i++) {
        int row = row0 + ty * 4 + i;
        if (row >= M) continue;
#pragma unroll
        for (int j = 0; j < 4; j++) {
            int col = col0 + tx * 4 + j;
            if (col >= Nc) continue;
            float v = acc[i][j];
            if (bias) v += bias[col];
            C[(size_t)row * ldc + ccol0 + col] = v;
        }
    }
}

// ---------------- gather (+ optional fused fp16 split of the result) ----------------
// out[dst, f] = (relu?)(out + dinv * sum_src g_P[src, f]); if SPLIT, also write hi/lo
// OUTS: 1=g_A, 2=g_B, 3=external
template <int OUTS, int SPLIT>
__global__ void k_gather(float* extOut, int CF, int relu) {
    float* out;
    if constexpr (OUTS == 1)      out = g_A;
    else if constexpr (OUTS == 2) out = g_B;
    else                          out = extOut;

    int dst = blockIdx.x;
    int b = g_rowptr[dst], t = g_rowptr[dst + 1];
    float s = g_dinv[dst];
    __shared__ int srcs[256];

    for (int f0 = 0; f0 < CF; f0 += 256) {
        int f = f0 + threadIdx.x;
        bool act = (f < CF);
        float acc = 0.f;
        for (int e0 = b; e0 < t; e0 += 256) {
            int cnt = t - e0; if (cnt > 256) cnt = 256;
            __syncthreads();
            if ((int)threadIdx.x < cnt) srcs[threadIdx.x] = g_csrc[e0 + threadIdx.x];
            __syncthreads();
            if (act) {
                for (int j = 0; j < cnt; j++)
                    acc += g_P[(size_t)srcs[j] * CF + f];
            }
        }
        if (act) {
            size_t o = (size_t)dst * CF + f;
            float v = out[o] + s * acc;
            if (relu) v = fmaxf(v, 0.f);
            out[o] = v;
            if constexpr (SPLIT) {
                __half h = __float2half(v);
                g_Ahi[o] = h;
                g_Alo[o] = __float2half(v - __half2float(h));
            }
        }
    }
}

// ---------------- host orchestration ----------------
static inline int cdiv(long long a, long long b) { return (int)((a + b - 1) / b); }

// weight offsets (elements); [Wr;Wl] packed per layer
#define WOFF_R1 0ull
#define WOFF_L1 1179648ull
#define WOFF_R2 2359296ull
#define WOFF_L2 3538944ull
#define WOFF_R3 4718592ull
#define WOFF_L3 5013504ull
#define WOFF_R4 5308416ull
#define WOFF_L4 5406720ull

extern "C" void kernel_launch(void* const* d_in, const int* in_sizes, int n_in,
                              void* d_out, int out_size) {
    const float* x  = (const float*)d_in[0];
    const int*   ei = (const int*)d_in[1];   // int32 (JAX downcasts int64)
    const float* Wl1 = (const float*)d_in[2],  *Wr1 = (const float*)d_in[3],  *b1 = (const float*)d_in[4];
    const float* Wl2 = (const float*)d_in[5],  *Wr2 = (const float*)d_in[6],  *b2 = (const float*)d_in[7];
    const float* Wl3 = (const float*)d_in[8],  *Wr3 = (const float*)d_in[9],  *b3 = (const float*)d_in[10];
    const float* Wl4 = (const float*)d_in[11], *Wr4 = (const float*)d_in[12], *b4 = (const float*)d_in[13];
    const float* Wl5 = (const float*)d_in[14], *Wr5 = (const float*)d_in[15], *b5 = (const float*)d_in[16];
    float* out = (float*)d_out;
    float* h4 = out;                          // [N,256]
    float* o5 = out + (size_t)NN * 256;       // [N,5]

    cudaFuncSetAttribute(k_mmagemm<1>, cudaFuncAttributeMaxDynamicSharedMemorySize, SMEM_DYN);
    cudaFuncSetAttribute(k_mmagemm<2>, cudaFuncAttributeMaxDynamicSharedMemorySize, SMEM_DYN);
    cudaFuncSetAttribute(k_mmagemm<3>, cudaFuncAttributeMaxDynamicSharedMemorySize, SMEM_DYN);

    // CSR build
    k_zero_int<<<cdiv(NN, 256), 256>>>();
    k_count<<<cdiv(EE, 256), 256>>>(ei);
    k_scan<<<1, 1024>>>();
    k_fill<<<cdiv(EE, 256), 256>>>(ei);
    k_sort<<<cdiv(NN, 256), 256>>>();

    // weight conversion (transposed, fp16)
    k_split_w<<<cdiv(768 * 1536, 256), 256>>>(Wr1, 768, 1536, WOFF_R1);
    k_split_w<<<cdiv(768 * 1536, 256), 256>>>(Wl1, 768, 1536, WOFF_L1);
    k_split_w<<<cdiv(1536 * 768, 256), 256>>>(Wr2, 1536, 768, WOFF_R2);
    k_split_w<<<cdiv(1536 * 768, 256), 256>>>(Wl2, 1536, 768, WOFF_L2);
    k_split_w<<<cdiv(768 * 384, 256), 256>>>(Wr3, 768, 384, WOFF_R3);
    k_split_w<<<cdiv(768 * 384, 256), 256>>>(Wl3, 768, 384, WOFF_L3);
    k_split_w<<<cdiv(384 * 256, 256), 256>>>(Wr4, 384, 256, WOFF_R4);
    k_split_w<<<cdiv(384 * 256, 256), 256>>>(Wl4, 384, 256, WOFF_L4);

    const int GX = cdiv(NN, 128);   // 157

    // ---- L1: x[768] -> g_A h1[1536] (fused Wr+Wl GEMM, Ntot=3072) ----
    k_split_ext<<<cdiv((long long)NN * 768, 256), 256>>>(x, (size_t)NN * 768);
    k_mmagemm<1><<<dim3(GX, 24), 256, SMEM_DYN>>>(nullptr, b1, WOFF_R1, NN, 768, 1536, 1536);
    k_gather<1, 1><<<NN, 256>>>(nullptr, 1536, 1);

    // ---- L2: g_A h1[1536] -> g_B h2[768] (Ntot=1536) ----
    k_mmagemm<2><<<dim3(GX, 12), 256, SMEM_DYN>>>(nullptr, b2, WOFF_R2, NN, 1536, 768, 768);
    k_gather<2, 1><<<NN, 256>>>(nullptr, 768, 1);

    // ---- L3: g_B h2[768] -> g_A h3[384] (Ntot=768) ----
    k_mmagemm<1><<<dim3(GX, 6), 256, SMEM_DYN>>>(nullptr, b3, WOFF_R3, NN, 768, 384, 384);
    k_gather<1, 1><<<NN, 256>>>(nullptr, 384, 1);

    // ---- L4: g_A h3[384] -> d_out h4[256] (Ntot=512) ----
    k_mmagemm<3><<<dim3(GX, 4), 256, SMEM_DYN>>>(h4, b4, WOFF_R4, NN, 384, 256, 256);
    k_gather<3, 0><<<NN, 256>>>(h4, 256, 1);

    // ---- L5: h4[256] -> o5[5] (SIMT, tiny) ----
    const int GX64 = cdiv(NN, 64);
    k_gemm<2, 3><<<dim3(GX64, 1), 256>>>(h4, o5, Wr5, b5, NN, 256, 5, 5, 5, 0);
    k_gemm<2, 0><<<dim3(GX64, 1), 256>>>(h4, nullptr, Wl5, nullptr, NN, 256, 5, 5, 5, 0);
    k_gather<3, 0><<<NN, 256>>>(o5, 5, 0);
}

// round 15
// speedup vs baseline: 6.2848x; 1.1689x over previous
#include <cuda_runtime.h>
#include <cuda_bf16.h>
#include <cuda_fp16.h>
#include <cstdint>

// ---------------- problem constants ----------------
#define NN 20000
#define EE 320000
// L1: 768->1536, L2: 1536->768, L3: 768->384, L4: 384->256, L5: 256->5

// ---------------- scratch (device globals) ----------------
__device__ float g_P[(size_t)NN * 1536];   // pre-aggregation linear output
__device__ float g_A[(size_t)NN * 1536];   // activation ping (h1 / h3)
__device__ float g_B[(size_t)NN * 768];    // activation pong (h2)
__device__ __half g_Ahi[(size_t)NN * 1536];  // fp16 split of current activations
__device__ __half g_Alo[(size_t)NN * 1536];
#define WSZ 5505024
__device__ __half g_Wh[WSZ];               // transposed [N,K] fp16 weights, [Wr;Wl] packed
__device__ float g_dinv[NN];
__device__ int   g_deg[NN];
__device__ int   g_rowptr[NN + 1];
__device__ int   g_cursor[NN];
__device__ int   g_csrc[EE];

// ---------------- PTX helpers (family-portable only) ----------------
__device__ __forceinline__ uint32_t smem_u32(const void* p) {
    uint32_t a;
    asm("{ .reg .u64 t; cvta.to.shared.u64 t, %1; cvt.u32.u64 %0, t; }" : "=r"(a) : "l"(p));
    return a;
}
__device__ __forceinline__ void ldsm4(uint32_t* r, uint32_t addr) {
    asm volatile("ldmatrix.sync.aligned.m8n8.x4.shared.b16 {%0,%1,%2,%3}, [%4];"
                 : "=r"(r[0]), "=r"(r[1]), "=r"(r[2]), "=r"(r[3]) : "r"(addr));
}
__device__ __forceinline__ void ldsm2(uint32_t* r, uint32_t addr) {
    asm volatile("ldmatrix.sync.aligned.m8n8.x2.shared.b16 {%0,%1}, [%2];"
                 : "=r"(r[0]), "=r"(r[1]) : "r"(addr));
}
__device__ __forceinline__ void mma_f16(float* c, const uint32_t* a, const uint32_t* b) {
    asm volatile(
        "mma.sync.aligned.m16n8k16.row.col.f32.f16.f16.f32 "
        "{%0,%1,%2,%3}, {%4,%5,%6,%7}, {%8,%9}, {%0,%1,%2,%3};"
        : "+f"(c[0]), "+f"(c[1]), "+f"(c[2]), "+f"(c[3])
        : "r"(a[0]), "r"(a[1]), "r"(a[2]), "r"(a[3]), "r"(b[0]), "r"(b[1]));
}
__device__ __forceinline__ void cp16(uint32_t saddr, const void* g, bool valid) {
    int sz = valid ? 16 : 0;
    asm volatile("cp.async.cg.shared.global [%0], [%1], 16, %2;"
                 :: "r"(saddr), "l"(g), "r"(sz));
}
#define CP_COMMIT() asm volatile("cp.async.commit_group;" ::: "memory")
#define CP_WAIT1()  asm volatile("cp.async.wait_group 1;" ::: "memory")

// ---------------- CSR build ----------------
__global__ void k_zero_int() {
    int i = blockIdx.x * blockDim.x + threadIdx.x;
    if (i < NN) { g_deg[i] = 0; g_cursor[i] = 0; }
}
__global__ void k_count(const int* __restrict__ ei) {
    int e = blockIdx.x * blockDim.x + threadIdx.x;
    if (e < EE) atomicAdd(&g_deg[ei[EE + e]], 1);
}
__global__ void k_scan() {
    __shared__ int sh[1024];
    int tid = threadIdx.x;
    int lo = tid * 20, hi = lo + 20;
    if (hi > NN) hi = NN;
    if (lo > NN) lo = NN;
    int s = 0;
    for (int i = lo; i < hi; i++) s += g_deg[i];
    sh[tid] = s;
    __syncthreads();
    for (int off = 1; off < 1024; off <<= 1) {
        int v = (tid >= off) ? sh[tid - off] : 0;
        __syncthreads();
        sh[tid] += v;
        __syncthreads();
    }
    int run = (tid > 0) ? sh[tid - 1] : 0;
    for (int i = lo; i < hi; i++) {
        g_rowptr[i] = run;
        int d = g_deg[i];
        run += d;
        g_dinv[i] = 1.0f / fmaxf((float)d, 1.0f);
    }
    if (tid == 0) g_rowptr[NN] = EE;
}
__global__ void k_fill(const int* __restrict__ ei) {
    int e = blockIdx.x * blockDim.x + threadIdx.x;
    if (e < EE) {
        int dst = ei[EE + e];
        int pos = atomicAdd(&g_cursor[dst], 1);
        g_csrc[g_rowptr[dst] + pos] = ei[e];
    }
}
__global__ void k_sort() {
    int n = blockIdx.x * blockDim.x + threadIdx.x;
    if (n >= NN) return;
    int b = g_rowptr[n], t = g_rowptr[n + 1];
    for (int i = b + 1; i < t; i++) {
        int v = g_csrc[i];
        int j = i - 1;
        while (j >= b && g_csrc[j] > v) { g_csrc[j + 1] = g_csrc[j]; j--; }
        g_csrc[j + 1] = v;
    }
}

// ---------------- fp32 -> fp16 hi/lo split (external input only) ----------------
__global__ void k_split_ext(const float* __restrict__ A, size_t n) {
    size_t i = (size_t)blockIdx.x * blockDim.x + threadIdx.x;
    if (i < n) {
        float v = A[i];
        __half h = __float2half(v);
        g_Ahi[i] = h;
        g_Alo[i] = __float2half(v - __half2float(h));
    }
}
// W [K,N] row-major -> transposed fp16 at g_Wh[woff + n*K + k]
__global__ void k_split_w(const float* __restrict__ W, int K, int N, size_t woff) {
    size_t i = (size_t)blockIdx.x * blockDim.x + threadIdx.x;
    if (i < (size_t)K * N) {
        int k = (int)(i / N), n = (int)(i % N);
        g_Wh[woff + (size_t)n * K + k] = __float2half(W[i]);
    }
}

// ---------------- fused dual-output mma.sync GEMM (fp16, 2-product, 3-stage) ------
// Computes A[M,K] @ [Wr;Wl]^T (packed [Ntot=2*Fo, K]).
// Col-blocks < Fo: dest = OUTS buffer (+bias). Col-blocks >= Fo: dest = g_P.
// Block 128x128, BK=32, 8 warps, warp tile 64x32, 3-stage cp.async pipeline.
// OUTS: 1=g_A, 2=g_B, 3=external
#define LDT 40                    // smem row stride in halves (32 data + 8 pad) = 80 B
#define REGSZ (128 * LDT * 2)     // one region: 10240 B
#define STGSZ (3 * REGSZ)         // stage: Ah, Al, Bh = 30720 B
#define NSTG 3
#define SMEM_DYN (NSTG * STGSZ)   // 92160 B

template <int OUTS>
__global__ void __launch_bounds__(256, 2)
k_mmagemm(float* extC, const float* __restrict__ bias,
          size_t woff, int M, int K, int Fo, int ldc1) {
    extern __shared__ __align__(16) char sdyn[];
    const uint32_t sb = smem_u32(sdyn);

    const int tid = threadIdx.x;
    const int lane = tid & 31, wid = tid >> 5;
    const int warp_m = wid & 1;       // 0..1 -> 64-row slab
    const int warp_n = wid >> 1;      // 0..3 -> 32-col slab
    const int row0 = blockIdx.x * 128, col0 = blockIdx.y * 128;

    const uint4* GAh = (const uint4*)g_Ahi;
    const uint4* GAl = (const uint4*)g_Alo;
    const uint4* GBh = (const uint4*)(g_Wh + woff);
    const int K8 = K >> 3;   // uint4 per row
    const int niter = K >> 5;

    float acc[4][4][4];      // [mt][nt][reg]
#pragma unroll
    for (int i = 0; i < 4; i++)
#pragma unroll
        for (int j = 0; j < 4; j++)
#pragma unroll
            for (int r = 0; r < 4; r++) acc[i][j][r] = 0.f;

    // stage loader: 3 regions x 512 uint4, 6 cp.async per thread
    auto load_stage = [&](int it, int s) {
        const int k8 = it << 2;
        const uint32_t base = sb + s * STGSZ;
#pragma unroll
        for (int h = 0; h < 2; ++h) {
            int i = tid + h * 256;
            int r = i >> 2, c4 = i & 3;
            uint32_t so = base + (uint32_t)(r * 5 + c4) * 16;
            int grow = row0 + r;
            bool v = grow < M;
            size_t go = v ? ((size_t)grow * K8 + k8 + c4) : 0;
            cp16(so,             GAh + go, v);
            cp16(so + REGSZ,     GAl + go, v);
            size_t gb = (size_t)(col0 + r) * K8 + k8 + c4;
            cp16(so + 2 * REGSZ, GBh + gb, true);
        }
    };

    // ldmatrix lane addressing
    const int a_row = lane & 15, a_kq = lane >> 4;       // x4: 16 rows, 2 col-halves
    const int b_row = lane & 7,  b_kq = (lane >> 3) & 1; // x2: 8 rows, 2 col-halves

    load_stage(0, 0);
    CP_COMMIT();
    if (1 < niter) { load_stage(1, 1); }
    CP_COMMIT();   // commit even if empty: keeps group count uniform

    for (int it = 0; it < niter; ++it) {
        const int s = it % NSTG;
        CP_WAIT1();            // stage 'it' group complete (groups retire in order)
        __syncthreads();       // all threads' copies for stage 'it' visible

        const uint32_t aAh = sb + s * STGSZ;
        const uint32_t aAl = aAh + REGSZ;
        const uint32_t aBh = aAh + 2 * REGSZ;

#pragma unroll
        for (int ks = 0; ks < 2; ++ks) {
            const int kk = ks * 16;
            uint32_t bh[4][2];
#pragma unroll
            for (int nt = 0; nt < 4; ++nt) {
                int n = warp_n * 32 + nt * 8 + b_row;
                uint32_t off = (uint32_t)(n * (LDT * 2) + (kk + b_kq * 8) * 2);
                ldsm2(bh[nt], aBh + off);
            }
#pragma unroll
            for (int mt = 0; mt < 4; ++mt) {
                int m = warp_m * 64 + mt * 16 + a_row;
                uint32_t off = (uint32_t)(m * (LDT * 2) + (kk + a_kq * 8) * 2);
                uint32_t ah[4], al[4];
                ldsm4(ah, aAh + off);
                ldsm4(al, aAl + off);
#pragma unroll
                for (int nt = 0; nt < 4; ++nt) {
                    mma_f16(acc[mt][nt], ah, bh[nt]);  // Ahi @ Bhi
                    mma_f16(acc[mt][nt], al, bh[nt]);  // Alo @ Bhi
                }
            }
        }
        // prefetch stage it+2 into the slot vacated by stage it-1
        if (it + 2 < niter) { load_stage(it + 2, (it + 2) % NSTG); }
        CP_COMMIT();           // uniform commit per iteration
    }

    // ---- epilogue with dual routing ----
    const bool isP = (col0 >= Fo);
    float* C;
    int ldc, colb;
    if (isP) {
        C = g_P; ldc = Fo; colb = col0 - Fo;
    } else {
        if constexpr (OUTS == 1)      C = g_A;
        else if constexpr (OUTS == 2) C = g_B;
        else                          C = extC;
        ldc = ldc1; colb = col0;
    }
    const int erow = lane >> 2, ecol = (lane & 3) * 2;
#pragma unroll
    for (int mt = 0; mt < 4; ++mt) {
        int mb = row0 + warp_m * 64 + mt * 16;
#pragma unroll
        for (int half = 0; half < 2; ++half) {
            int row = mb + erow + half * 8;
            if (row >= M) continue;
            float* Cr = C + (size_t)row * ldc;
#pragma unroll
            for (int nt = 0; nt < 4; ++nt) {
                int col = colb + warp_n * 32 + nt * 8 + ecol;
                float v0 = acc[mt][nt][half * 2 + 0];
                float v1 = acc[mt][nt][half * 2 + 1];
                if (!isP && bias) { v0 += bias[col]; v1 += bias[col + 1]; }
                Cr[col] = v0;
                Cr[col + 1] = v1;
            }
        }
    }
}

// ---------------- SIMT GEMM (kept for L5, Nc=5) ----------------
template <int INS, int OUTS>
__global__ void __launch_bounds__(256)
k_gemm(const float* extA, float* extC,
       const float* __restrict__ Bw, const float* __restrict__ bias,
       int M, int K, int Nc, int ldb, int ldc, int ccol0) {
    const float* A;
    if constexpr (INS == 0)      A = g_A;
    else if constexpr (INS == 1) A = g_B;
    else                         A = extA;
    float* C;
    if constexpr (OUTS == 0)      C = g_P;
    else if constexpr (OUTS == 1) C = g_A;
    else if constexpr (OUTS == 2) C = g_B;
    else                          C = extC;

    __shared__ float As[16][64];
    __shared__ float Bs[16][65];
    int tid = threadIdx.x;
    int tx = tid & 15, ty = tid >> 4;
    int row0 = blockIdx.x * 64, col0 = blockIdx.y * 64;

    float acc[4][4];
#pragma unroll
    for (int i = 0; i < 4; i++)
#pragma unroll
        for (int j = 0; j < 4; j++) acc[i][j] = 0.f;

    for (int k0 = 0; k0 < K; k0 += 16) {
        for (int i = tid; i < 64 * 16; i += 256) {
            int m = i >> 4, kk = i & 15;
            int row = row0 + m;
            As[kk][m] = (row < M) ? A[(size_t)row * K + k0 + kk] : 0.f;
        }
        for (int i = tid; i < 16 * 64; i += 256) {
            int kk = i >> 6, n = i & 63;
            int col = col0 + n;
            Bs[kk][n] = (col < Nc) ? Bw[(size_t)(k0 + kk) * ldb + col] : 0.f;
        }
        __syncthreads();
#pragma unroll
        for (int kk = 0; kk < 16; ++kk) {
            float av[4], bv[4];
#pragma unroll
            for (int i = 0; i < 4; i++) av[i] = As[kk][ty * 4 + i];
#pragma unroll
            for (int j = 0; j < 4; j++) bv[j] = Bs[kk][tx * 4 + j];
#pragma unroll
            for (int i = 0; i < 4; i++)
#pragma unroll
                for (int j = 0; j < 4; j++)
                    acc[i][j] = fmaf(av[i], bv[j], acc[i][j]);
        }
        __syncthreads();
    }
#pragma unroll
    for (int i = 0; i < 4; i++) {
        int row = row0 + ty * 4 + i;
        if (row >= M) continue;
#pragma unroll
        for (int j = 0; j < 4; j++) {
            int col = col0 + tx * 4 + j;
            if (col >= Nc) continue;
            float v = acc[i][j];
            if (bias) v += bias[col];
            C[(size_t)row * ldc + ccol0 + col] = v;
        }
    }
}

// ---------------- gather v2: no smem, no barriers, float4 per thread --------------
// out[dst, f] = (relu?)(out + dinv * sum_src g_P[src, f]); if SPLIT, fp16 hi/lo too
// OUTS: 1=g_A, 2=g_B, 3=external.  VEC: 4 (CF%4==0) or 1 (scalar, for CF=5)
template <int OUTS, int SPLIT, int VEC>
__global__ void k_gather(float* extOut, int CF, int relu) {
    float* out;
    if constexpr (OUTS == 1)      out = g_A;
    else if constexpr (OUTS == 2) out = g_B;
    else                          out = extOut;

    const int dst = blockIdx.x;
    const int b = g_rowptr[dst], t = g_rowptr[dst + 1];
    const float s = g_dinv[dst];

    if constexpr (VEC == 4) {
        for (int f = threadIdx.x * 4; f < CF; f += blockDim.x * 4) {
            float ax = 0.f, ay = 0.f, az = 0.f, aw = 0.f;
            for (int j = b; j < t; j++) {
                int src = __ldg(&g_csrc[j]);           // uniform -> L1 broadcast
                float4 p = *(const float4*)(g_P + (size_t)src * CF + f);
                ax += p.x; ay += p.y; az += p.z; aw += p.w;
            }
            size_t o = (size_t)dst * CF + f;
            float4 v = *(float4*)(out + o);
            v.x += s * ax; v.y += s * ay; v.z += s * az; v.w += s * aw;
            if (relu) {
                v.x = fmaxf(v.x, 0.f); v.y = fmaxf(v.y, 0.f);
                v.z = fmaxf(v.z, 0.f); v.w = fmaxf(v.w, 0.f);
            }
            *(float4*)(out + o) = v;
            if constexpr (SPLIT) {
                __half h0 = __float2half(v.x), h1 = __float2half(v.y);
                __half h2 = __float2half(v.z), h3 = __float2half(v.w);
                *(__half2*)(g_Ahi + o)     = __halves2half2(h0, h1);
                *(__half2*)(g_Ahi + o + 2) = __halves2half2(h2, h3);
                *(__half2*)(g_Alo + o) = __halves2half2(
                    __float2half(v.x - __half2float(h0)),
                    __float2half(v.y - __half2float(h1)));
                *(__half2*)(g_Alo + o + 2) = __halves2half2(
                    __float2half(v.z - __half2float(h2)),
                    __float2half(v.w - __half2float(h3)));
            }
        }
    } else {
        for (int f = threadIdx.x; f < CF; f += blockDim.x) {
            float acc = 0.f;
            for (int j = b; j < t; j++) {
                int src = __ldg(&g_csrc[j]);
                acc += g_P[(size_t)src * CF + f];
            }
            size_t o = (size_t)dst * CF + f;
            float v = out[o] + s * acc;
            if (relu) v = fmaxf(v, 0.f);
            out[o] = v;
        }
    }
}

// ---------------- host orchestration ----------------
static inline int cdiv(long long a, long long b) { return (int)((a + b - 1) / b); }

// weight offsets (elements); [Wr;Wl] packed per layer
#define WOFF_R1 0ull
#define WOFF_L1 1179648ull
#define WOFF_R2 2359296ull
#define WOFF_L2 3538944ull
#define WOFF_R3 4718592ull
#define WOFF_L3 5013504ull
#define WOFF_R4 5308416ull
#define WOFF_L4 5406720ull

extern "C" void kernel_launch(void* const* d_in, const int* in_sizes, int n_in,
                              void* d_out, int out_size) {
    const float* x  = (const float*)d_in[0];
    const int*   ei = (const int*)d_in[1];   // int32 (JAX downcasts int64)
    const float* Wl1 = (const float*)d_in[2],  *Wr1 = (const float*)d_in[3],  *b1 = (const float*)d_in[4];
    const float* Wl2 = (const float*)d_in[5],  *Wr2 = (const float*)d_in[6],  *b2 = (const float*)d_in[7];
    const float* Wl3 = (const float*)d_in[8],  *Wr3 = (const float*)d_in[9],  *b3 = (const float*)d_in[10];
    const float* Wl4 = (const float*)d_in[11], *Wr4 = (const float*)d_in[12], *b4 = (const float*)d_in[13];
    const float* Wl5 = (const float*)d_in[14], *Wr5 = (const float*)d_in[15], *b5 = (const float*)d_in[16];
    float* out = (float*)d_out;
    float* h4 = out;                          // [N,256]
    float* o5 = out + (size_t)NN * 256;       // [N,5]

    cudaFuncSetAttribute(k_mmagemm<1>, cudaFuncAttributeMaxDynamicSharedMemorySize, SMEM_DYN);
    cudaFuncSetAttribute(k_mmagemm<2>, cudaFuncAttributeMaxDynamicSharedMemorySize, SMEM_DYN);
    cudaFuncSetAttribute(k_mmagemm<3>, cudaFuncAttributeMaxDynamicSharedMemorySize, SMEM_DYN);

    // CSR build
    k_zero_int<<<cdiv(NN, 256), 256>>>();
    k_count<<<cdiv(EE, 256), 256>>>(ei);
    k_scan<<<1, 1024>>>();
    k_fill<<<cdiv(EE, 256), 256>>>(ei);
    k_sort<<<cdiv(NN, 256), 256>>>();

    // weight conversion (transposed, fp16)
    k_split_w<<<cdiv(768 * 1536, 256), 256>>>(Wr1, 768, 1536, WOFF_R1);
    k_split_w<<<cdiv(768 * 1536, 256), 256>>>(Wl1, 768, 1536, WOFF_L1);
    k_split_w<<<cdiv(1536 * 768, 256), 256>>>(Wr2, 1536, 768, WOFF_R2);
    k_split_w<<<cdiv(1536 * 768, 256), 256>>>(Wl2, 1536, 768, WOFF_L2);
    k_split_w<<<cdiv(768 * 384, 256), 256>>>(Wr3, 768, 384, WOFF_R3);
    k_split_w<<<cdiv(768 * 384, 256), 256>>>(Wl3, 768, 384, WOFF_L3);
    k_split_w<<<cdiv(384 * 256, 256), 256>>>(Wr4, 384, 256, WOFF_R4);
    k_split_w<<<cdiv(384 * 256, 256), 256>>>(Wl4, 384, 256, WOFF_L4);

    const int GX = cdiv(NN, 128);   // 157

    // ---- L1: x[768] -> g_A h1[1536] (fused Wr+Wl GEMM, Ntot=3072) ----
    k_split_ext<<<cdiv((long long)NN * 768, 256), 256>>>(x, (size_t)NN * 768);
    k_mmagemm<1><<<dim3(GX, 24), 256, SMEM_DYN>>>(nullptr, b1, WOFF_R1, NN, 768, 1536, 1536);
    k_gather<1, 1, 4><<<NN, 256>>>(nullptr, 1536, 1);

    // ---- L2: g_A h1[1536] -> g_B h2[768] (Ntot=1536) ----
    k_mmagemm<2><<<dim3(GX, 12), 256, SMEM_DYN>>>(nullptr, b2, WOFF_R2, NN, 1536, 768, 768);
    k_gather<2, 1, 4><<<NN, 192>>>(nullptr, 768, 1);

    // ---- L3: g_B h2[768] -> g_A h3[384] (Ntot=768) ----
    k_mmagemm<1><<<dim3(GX, 6), 256, SMEM_DYN>>>(nullptr, b3, WOFF_R3, NN, 768, 384, 384);
    k_gather<1, 1, 4><<<NN, 96>>>(nullptr, 384, 1);

    // ---- L4: g_A h3[384] -> d_out h4[256] (Ntot=512) ----
    k_mmagemm<3><<<dim3(GX, 4), 256, SMEM_DYN>>>(h4, b4, WOFF_R4, NN, 384, 256, 256);
    k_gather<3, 0, 4><<<NN, 64>>>(h4, 256, 1);

    // ---- L5: h4[256] -> o5[5] (SIMT, tiny) ----
    const int GX64 = cdiv(NN, 64);
    k_gemm<2, 3><<<dim3(GX64, 1), 256>>>(h4, o5, Wr5, b5, NN, 256, 5, 5, 5, 0);
    k_gemm<2, 0><<<dim3(GX64, 1), 256>>>(h4, nullptr, Wl5, nullptr, NN, 256, 5, 5, 5, 0);
    k_gather<3, 0, 1><<<NN, 32>>>(o5, 5, 0);
}

// round 17
// speedup vs baseline: 6.6242x; 1.0540x over previous
#include <cuda_runtime.h>
#include <cuda_bf16.h>
#include <cuda_fp16.h>
#include <cstdint>

// ---------------- problem constants ----------------
#define NN 20000
#define EE 320000
// L1: 768->1536, L2: 1536->768, L3: 768->384, L4: 384->256, L5: 256->5

// ---------------- scratch (device globals) ----------------
__device__ float g_P[(size_t)NN * 1536];   // pre-aggregation linear output
__device__ float g_A[(size_t)NN * 1536];   // activation ping (h1 / h3)
__device__ float g_B[(size_t)NN * 768];    // activation pong (h2)
__device__ __half g_Ahi[(size_t)NN * 1536];  // fp16 split of current activations
__device__ __half g_Alo[(size_t)NN * 1536];
#define WSZ 5505024
__device__ __half g_Wh[WSZ];               // transposed [N,K] fp16 weights, [Wr;Wl] packed
__device__ float g_dinv[NN];
__device__ int   g_deg[NN];
__device__ int   g_rowptr[NN + 1];
__device__ int   g_cursor[NN];
__device__ int   g_csrc[EE];

// weight offsets (elements); [Wr;Wl] packed per layer
#define WOFF_R1 0ull
#define WOFF_L1 1179648ull
#define WOFF_R2 2359296ull
#define WOFF_L2 3538944ull
#define WOFF_R3 4718592ull
#define WOFF_L3 5013504ull
#define WOFF_R4 5308416ull
#define WOFF_L4 5406720ull

// ---------------- PTX helpers (family-portable only) ----------------
__device__ __forceinline__ uint32_t smem_u32(const void* p) {
    uint32_t a;
    asm("{ .reg .u64 t; cvta.to.shared.u64 t, %1; cvt.u32.u64 %0, t; }" : "=r"(a) : "l"(p));
    return a;
}
__device__ __forceinline__ void ldsm4(uint32_t* r, uint32_t addr) {
    asm volatile("ldmatrix.sync.aligned.m8n8.x4.shared.b16 {%0,%1,%2,%3}, [%4];"
                 : "=r"(r[0]), "=r"(r[1]), "=r"(r[2]), "=r"(r[3]) : "r"(addr));
}
__device__ __forceinline__ void mma_f16(float* c, const uint32_t* a, const uint32_t* b) {
    asm volatile(
        "mma.sync.aligned.m16n8k16.row.col.f32.f16.f16.f32 "
        "{%0,%1,%2,%3}, {%4,%5,%6,%7}, {%8,%9}, {%0,%1,%2,%3};"
        : "+f"(c[0]), "+f"(c[1]), "+f"(c[2]), "+f"(c[3])
        : "r"(a[0]), "r"(a[1]), "r"(a[2]), "r"(a[3]), "r"(b[0]), "r"(b[1]));
}
__device__ __forceinline__ void cp16(uint32_t saddr, const void* g, bool valid) {
    int sz = valid ? 16 : 0;
    asm volatile("cp.async.cg.shared.global [%0], [%1], 16, %2;"
                 :: "r"(saddr), "l"(g), "r"(sz));
}
#define CP_COMMIT() asm volatile("cp.async.commit_group;" ::: "memory")
#define CP_WAIT1()  asm volatile("cp.async.wait_group 1;" ::: "memory")

// ---------------- CSR build ----------------
__global__ void k_zero_int() {
    int i = blockIdx.x * blockDim.x + threadIdx.x;
    if (i < NN) { g_deg[i] = 0; g_cursor[i] = 0; }
}
__global__ void k_count(const int* __restrict__ ei) {
    int e = blockIdx.x * blockDim.x + threadIdx.x;
    if (e < EE) atomicAdd(&g_deg[ei[EE + e]], 1);
}
__global__ void k_scan() {
    __shared__ int sh[1024];
    int tid = threadIdx.x;
    int lo = tid * 20, hi = lo + 20;
    if (hi > NN) hi = NN;
    if (lo > NN) lo = NN;
    int s = 0;
    for (int i = lo; i < hi; i++) s += g_deg[i];
    sh[tid] = s;
    __syncthreads();
    for (int off = 1; off < 1024; off <<= 1) {
        int v = (tid >= off) ? sh[tid - off] : 0;
        __syncthreads();
        sh[tid] += v;
        __syncthreads();
    }
    int run = (tid > 0) ? sh[tid - 1] : 0;
    for (int i = lo; i < hi; i++) {
        g_rowptr[i] = run;
        int d = g_deg[i];
        run += d;
        g_dinv[i] = 1.0f / fmaxf((float)d, 1.0f);
    }
    if (tid == 0) g_rowptr[NN] = EE;
}
__global__ void k_fill(const int* __restrict__ ei) {
    int e = blockIdx.x * blockDim.x + threadIdx.x;
    if (e < EE) {
        int dst = ei[EE + e];
        int pos = atomicAdd(&g_cursor[dst], 1);
        g_csrc[g_rowptr[dst] + pos] = ei[e];
    }
}
__global__ void k_sort() {
    int n = blockIdx.x * blockDim.x + threadIdx.x;
    if (n >= NN) return;
    int b = g_rowptr[n], t = g_rowptr[n + 1];
    for (int i = b + 1; i < t; i++) {
        int v = g_csrc[i];
        int j = i - 1;
        while (j >= b && g_csrc[j] > v) { g_csrc[j + 1] = g_csrc[j]; j--; }
        g_csrc[j + 1] = v;
    }
}

// ---------------- fp32 -> fp16 hi/lo split (external input only) ----------------
__global__ void k_split_ext(const float* __restrict__ A, size_t n) {
    size_t i = (size_t)blockIdx.x * blockDim.x + threadIdx.x;
    if (i < n) {
        float v = A[i];
        __half h = __float2half(v);
        g_Ahi[i] = h;
        g_Alo[i] = __float2half(v - __half2float(h));
    }
}

// ---------------- single-launch weight transpose+convert for all 4 tc layers -----
// Packed layout covers [Wr1;Wl1;Wr2;Wl2;Wr3;Wl3;Wr4;Wl4]; each W is [K,N] row-major
// in gmem, stored transposed fp16 at g_Wh[woff + n*K + k].
__global__ void k_split_w_all(const float* __restrict__ Wr1, const float* __restrict__ Wl1,
                              const float* __restrict__ Wr2, const float* __restrict__ Wl2,
                              const float* __restrict__ Wr3, const float* __restrict__ Wl3,
                              const float* __restrict__ Wr4, const float* __restrict__ Wl4) {
    for (size_t i = (size_t)blockIdx.x * blockDim.x + threadIdx.x; i < WSZ;
         i += (size_t)gridDim.x * blockDim.x) {
        const float* W; int K, N; size_t woff;
        if (i < WOFF_L1)      { W = Wr1; K = 768;  N = 1536; woff = WOFF_R1; }
        else if (i < WOFF_R2) { W = Wl1; K = 768;  N = 1536; woff = WOFF_L1; }
        else if (i < WOFF_L2) { W = Wr2; K = 1536; N = 768;  woff = WOFF_R2; }
        else if (i < WOFF_R3) { W = Wl2; K = 1536; N = 768;  woff = WOFF_L2; }
        else if (i < WOFF_L3) { W = Wr3; K = 768;  N = 384;  woff = WOFF_R3; }
        else if (i < WOFF_R4) { W = Wl3; K = 768;  N = 384;  woff = WOFF_L3; }
        else if (i < WOFF_L4) { W = Wr4; K = 384;  N = 256;  woff = WOFF_R4; }
        else                  { W = Wl4; K = 384;  N = 256;  woff = WOFF_L4; }
        size_t j = i - woff;
        int k = (int)(j / N), n = (int)(j % N);
        g_Wh[woff + (size_t)n * K + k] = __float2half(W[j]);
    }
}

// ---------------- fused dual-output mma.sync GEMM (fp16, 2-product, 3-stage) ------
// Computes A[M,K] @ [Wr;Wl]^T (packed [Ntot=2*Fo, K]).
// Col-blocks < Fo: dest = OUTS buffer (+bias). Col-blocks >= Fo: dest = g_P.
// Block 128x128, BK=32, 8 warps, warp tile 64x32, 3-stage cp.async pipeline.
// OUTS: 1=g_A, 2=g_B, 3=external
#define LDT 40                    // smem row stride in halves (32 data + 8 pad) = 80 B
#define REGSZ (128 * LDT * 2)     // one region: 10240 B
#define STGSZ (3 * REGSZ)         // stage: Ah, Al, Bh = 30720 B
#define NSTG 3
#define SMEM_DYN (NSTG * STGSZ)   // 92160 B

template <int OUTS>
__global__ void __launch_bounds__(256, 2)
k_mmagemm(float* extC, const float* __restrict__ bias,
          size_t woff, int M, int K, int Fo, int ldc1) {
    extern __shared__ __align__(16) char sdyn[];
    const uint32_t sb = smem_u32(sdyn);

    const int tid = threadIdx.x;
    const int lane = tid & 31, wid = tid >> 5;
    const int warp_m = wid & 1;       // 0..1 -> 64-row slab
    const int warp_n = wid >> 1;      // 0..3 -> 32-col slab
    const int row0 = blockIdx.x * 128, col0 = blockIdx.y * 128;

    const uint4* GAh = (const uint4*)g_Ahi;
    const uint4* GAl = (const uint4*)g_Alo;
    const uint4* GBh = (const uint4*)(g_Wh + woff);
    const int K8 = K >> 3;   // uint4 per row
    const int niter = K >> 5;

    float acc[4][4][4];      // [mt][nt][reg]
#pragma unroll
    for (int i = 0; i < 4; i++)
#pragma unroll
        for (int j = 0; j < 4; j++)
#pragma unroll
            for (int r = 0; r < 4; r++) acc[i][j][r] = 0.f;

    // stage loader: 3 regions x 512 uint4, 6 cp.async per thread
    auto load_stage = [&](int it, int s) {
        const int k8 = it << 2;
        const uint32_t base = sb + s * STGSZ;
#pragma unroll
        for (int h = 0; h < 2; ++h) {
            int i = tid + h * 256;
            int r = i >> 2, c4 = i & 3;
            uint32_t so = base + (uint32_t)(r * 5 + c4) * 16;
            int grow = row0 + r;
            bool v = grow < M;
            size_t go = v ? ((size_t)grow * K8 + k8 + c4) : 0;
            cp16(so,             GAh + go, v);
            cp16(so + REGSZ,     GAl + go, v);
            size_t gb = (size_t)(col0 + r) * K8 + k8 + c4;
            cp16(so + 2 * REGSZ, GBh + gb, true);
        }
    };

    // ldmatrix lane addressing
    const int a_row = lane & 15, a_kq = lane >> 4;   // x4 A: 16 rows, 2 col-halves
    const int b_g = lane >> 3, b_r = lane & 7;       // x4 B: 4 groups of 8 rows

    load_stage(0, 0);
    CP_COMMIT();
    if (1 < niter) { load_stage(1, 1); }
    CP_COMMIT();   // commit even if empty: keeps group count uniform

    for (int it = 0; it < niter; ++it) {
        const int s = it % NSTG;
        CP_WAIT1();            // stage 'it' group complete (groups retire in order)
        __syncthreads();       // all threads' copies for stage 'it' visible

        const uint32_t aAh = sb + s * STGSZ;
        const uint32_t aAl = aAh + REGSZ;
        const uint32_t aBh = aAh + 2 * REGSZ;

#pragma unroll
        for (int ks = 0; ks < 2; ++ks) {
            const int kk = ks * 16;
            // B frags: pairs of n-tiles per ldsm4: matrices = (p,k0),(p,k8),(p+1,k0),(p+1,k8)
            uint32_t bh[4][2];
#pragma unroll
            for (int p = 0; p < 4; p += 2) {
                int n = warp_n * 32 + (p + (b_g >> 1)) * 8 + b_r;
                uint32_t off = (uint32_t)(n * (LDT * 2) + (kk + (b_g & 1) * 8) * 2);
                uint32_t rr[4];
                ldsm4(rr, aBh + off);
                bh[p][0] = rr[0]; bh[p][1] = rr[1];
                bh[p + 1][0] = rr[2]; bh[p + 1][1] = rr[3];
            }
#pragma unroll
            for (int mt = 0; mt < 4; ++mt) {
                int m = warp_m * 64 + mt * 16 + a_row;
                uint32_t off = (uint32_t)(m * (LDT * 2) + (kk + a_kq * 8) * 2);
                uint32_t ah[4], al[4];
                ldsm4(ah, aAh + off);
                ldsm4(al, aAl + off);
#pragma unroll
                for (int nt = 0; nt < 4; ++nt) {
                    mma_f16(acc[mt][nt], ah, bh[nt]);  // Ahi @ Bhi
                    mma_f16(acc[mt][nt], al, bh[nt]);  // Alo @ Bhi
                }
            }
        }
        // prefetch stage it+2 into the slot vacated by stage it-1
        if (it + 2 < niter) { load_stage(it + 2, (it + 2) % NSTG); }
        CP_COMMIT();           // uniform commit per iteration
    }

    // ---- epilogue with dual routing ----
    const bool isP = (col0 >= Fo);
    float* C;
    int ldc, colb;
    if (isP) {
        C = g_P; ldc = Fo; colb = col0 - Fo;
    } else {
        if constexpr (OUTS == 1)      C = g_A;
        else if constexpr (OUTS == 2) C = g_B;
        else                          C = extC;
        ldc = ldc1; colb = col0;
    }
    const int erow = lane >> 2, ecol = (lane & 3) * 2;
#pragma unroll
    for (int mt = 0; mt < 4; ++mt) {
        int mb = row0 + warp_m * 64 + mt * 16;
#pragma unroll
        for (int half = 0; half < 2; ++half) {
            int row = mb + erow + half * 8;
            if (row >= M) continue;
            float* Cr = C + (size_t)row * ldc;
#pragma unroll
            for (int nt = 0; nt < 4; ++nt) {
                int col = colb + warp_n * 32 + nt * 8 + ecol;
                float v0 = acc[mt][nt][half * 2 + 0];
                float v1 = acc[mt][nt][half * 2 + 1];
                if (!isP && bias) { v0 += bias[col]; v1 += bias[col + 1]; }
                Cr[col] = v0;
                Cr[col + 1] = v1;
            }
        }
    }
}

// ---------------- L5 fused: o5 = h4@Wr5 + b5 ; g_P[:, :5] = h4@Wl5 ----------------
// One warp per node; weights staged in smem.
__global__ void __launch_bounds__(256)
k_l5(const float* __restrict__ h4, const float* __restrict__ Wr5,
     const float* __restrict__ Wl5, const float* __restrict__ b5,
     float* __restrict__ o5) {
    __shared__ float sW[2560];   // [256][5] Wr5, then [256][5] Wl5
    int tid = threadIdx.x;
    for (int i = tid; i < 1280; i += blockDim.x) {
        sW[i] = Wr5[i];
        sW[1280 + i] = Wl5[i];
    }
    __syncthreads();
    int warp = tid >> 5, lane = tid & 31;
    int node = blockIdx.x * 8 + warp;
    if (node >= NN) return;
    const float* hrow = h4 + (size_t)node * 256;
    float h[8];
#pragma unroll
    for (int q = 0; q < 8; q++) h[q] = hrow[lane + q * 32];
#pragma unroll
    for (int c = 0; c < 5; c++) {
        float sr = 0.f, sl = 0.f;
#pragma unroll
        for (int q = 0; q < 8; q++) {
            int k = lane + q * 32;
            sr += h[q] * sW[k * 5 + c];
            sl += h[q] * sW[1280 + k * 5 + c];
        }
#pragma unroll
        for (int o = 16; o > 0; o >>= 1) {
            sr += __shfl_down_sync(0xFFFFFFFFu, sr, o);
            sl += __shfl_down_sync(0xFFFFFFFFu, sl, o);
        }
        if (lane == 0) {
            o5[(size_t)node * 5 + c] = sr + b5[c];
            g_P[(size_t)node * 5 + c] = sl;
        }
    }
}

// ---------------- gather: no smem, no barriers, float4 per thread --------------
// out[dst, f] = (relu?)(out + dinv * sum_src g_P[src, f]); if SPLIT, fp16 hi/lo too
// OUTS: 1=g_A, 2=g_B, 3=external.  VEC: 4 (CF%4==0) or 1 (scalar, for CF=5)
template <int OUTS, int SPLIT, int VEC>
__global__ void k_gather(float* extOut, int CF, int relu) {
    float* out;
    if constexpr (OUTS == 1)      out = g_A;
    else if constexpr (OUTS == 2) out = g_B;
    else                          out = extOut;

    const int dst = blockIdx.x;
    const int b = g_rowptr[dst], t = g_rowptr[dst + 1];
    const float s = g_dinv[dst];

    if constexpr (VEC == 4) {
        for (int f = threadIdx.x * 4; f < CF; f += blockDim.x * 4) {
            float ax = 0.f, ay = 0.f, az = 0.f, aw = 0.f;
            for (int j = b; j < t; j++) {
                int src = __ldg(&g_csrc[j]);           // uniform -> L1 broadcast
                float4 p = *(const float4*)(g_P + (size_t)src * CF + f);
                ax += p.x; ay += p.y; az += p.z; aw += p.w;
            }
            size_t o = (size_t)dst * CF + f;
            float4 v = *(float4*)(out + o);
            v.x += s * ax; v.y += s * ay; v.z += s * az; v.w += s * aw;
            if (relu) {
                v.x = fmaxf(v.x, 0.f); v.y = fmaxf(v.y, 0.f);
                v.z = fmaxf(v.z, 0.f); v.w = fmaxf(v.w, 0.f);
            }
            *(float4*)(out + o) = v;
            if constexpr (SPLIT) {
                __half h0 = __float2half(v.x), h1 = __float2half(v.y);
                __half h2 = __float2half(v.z), h3 = __float2half(v.w);
                *(__half2*)(g_Ahi + o)     = __halves2half2(h0, h1);
                *(__half2*)(g_Ahi + o + 2) = __halves2half2(h2, h3);
                *(__half2*)(g_Alo + o) = __halves2half2(
                    __float2half(v.x - __half2float(h0)),
                    __float2half(v.y - __half2float(h1)));
                *(__half2*)(g_Alo + o + 2) = __halves2half2(
                    __float2half(v.z - __half2float(h2)),
                    __float2half(v.w - __half2float(h3)));
            }
        }
    } else {
        for (int f = threadIdx.x; f < CF; f += blockDim.x) {
            float acc = 0.f;
            for (int j = b; j < t; j++) {
                int src = __ldg(&g_csrc[j]);
                acc += g_P[(size_t)src * CF + f];
            }
            size_t o = (size_t)dst * CF + f;
            float v = out[o] + s * acc;
            if (relu) v = fmaxf(v, 0.f);
            out[o] = v;
        }
    }
}

// ---------------- host orchestration ----------------
static inline int cdiv(long long a, long long b) { return (int)((a + b - 1) / b); }

extern "C" void kernel_launch(void* const* d_in, const int* in_sizes, int n_in,
                              void* d_out, int out_size) {
    const float* x  = (const float*)d_in[0];
    const int*   ei = (const int*)d_in[1];   // int32 (JAX downcasts int64)
    const float* Wl1 = (const float*)d_in[2],  *Wr1 = (const float*)d_in[3],  *b1 = (const float*)d_in[4];
    const float* Wl2 = (const float*)d_in[5],  *Wr2 = (const float*)d_in[6],  *b2 = (const float*)d_in[7];
    const float* Wl3 = (const float*)d_in[8],  *Wr3 = (const float*)d_in[9],  *b3 = (const float*)d_in[10];
    const float* Wl4 = (const float*)d_in[11], *Wr4 = (const float*)d_in[12], *b4 = (const float*)d_in[13];
    const float* Wl5 = (const float*)d_in[14], *Wr5 = (const float*)d_in[15], *b5 = (const float*)d_in[16];
    float* out = (float*)d_out;
    float* h4 = out;                          // [N,256]
    float* o5 = out + (size_t)NN * 256;       // [N,5]

    cudaFuncSetAttribute(k_mmagemm<1>, cudaFuncAttributeMaxDynamicSharedMemorySize, SMEM_DYN);
    cudaFuncSetAttribute(k_mmagemm<2>, cudaFuncAttributeMaxDynamicSharedMemorySize, SMEM_DYN);
    cudaFuncSetAttribute(k_mmagemm<3>, cudaFuncAttributeMaxDynamicSharedMemorySize, SMEM_DYN);

    // CSR build
    k_zero_int<<<cdiv(NN, 256), 256>>>();
    k_count<<<cdiv(EE, 256), 256>>>(ei);
    k_scan<<<1, 1024>>>();
    k_fill<<<cdiv(EE, 256), 256>>>(ei);
    k_sort<<<cdiv(NN, 256), 256>>>();

    // weight conversion (transposed, fp16) — single launch
    k_split_w_all<<<2048, 256>>>(Wr1, Wl1, Wr2, Wl2, Wr3, Wl3, Wr4, Wl4);

    const int GX = cdiv(NN, 128);   // 157

    // ---- L1: x[768] -> g_A h1[1536] (fused Wr+Wl GEMM, Ntot=3072) ----
    k_split_ext<<<cdiv((long long)NN * 768, 256), 256>>>(x, (size_t)NN * 768);
    k_mmagemm<1><<<dim3(GX, 24), 256, SMEM_DYN>>>(nullptr, b1, WOFF_R1, NN, 768, 1536, 1536);
    k_gather<1, 1, 4><<<NN, 256>>>(nullptr, 1536, 1);

    // ---- L2: g_A h1[1536] -> g_B h2[768] (Ntot=1536) ----
    k_mmagemm<2><<<dim3(GX, 12), 256, SMEM_DYN>>>(nullptr, b2, WOFF_R2, NN, 1536, 768, 768);
    k_gather<2, 1, 4><<<NN, 192>>>(nullptr, 768, 1);

    // ---- L3: g_B h2[768] -> g_A h3[384] (Ntot=768) ----
    k_mmagemm<1><<<dim3(GX, 6), 256, SMEM_DYN>>>(nullptr, b3, WOFF_R3, NN, 768, 384, 384);
    k_gather<1, 1, 4><<<NN, 96>>>(nullptr, 384, 1);

    // ---- L4: g_A h3[384] -> d_out h4[256] (Ntot=512) ----
    k_mmagemm<3><<<dim3(GX, 4), 256, SMEM_DYN>>>(h4, b4, WOFF_R4, NN, 384, 256, 256);
    k_gather<3, 0, 4><<<NN, 64>>>(h4, 256, 1);

    // ---- L5: h4[256] -> o5[5] (fused warp-per-node) ----
    k_l5<<<cdiv(NN, 8), 256>>>(h4, Wr5, Wl5, b5, o5);
    k_gather<3, 0, 1><<<NN, 32>>>(o5, 5, 0);
}